// round 2
// baseline (speedup 1.0000x reference)
#include <cuda_runtime.h>

#define N_NODES 25000
#define N_EDGES 300000
#define N_GRAPHS 256

#define DINL __device__ __forceinline__

// ---------------- helpers ----------------

DINL float sp(float x) {
    // numerically stable softplus: max(x,0) + log1p(exp(-|x|))
    return fmaxf(x, 0.f) + __logf(1.f + __expf(-fabsf(x)));
}

DINL unsigned long long pk2(float lo, float hi) {
    unsigned long long r;
    asm("mov.b64 %0, {%1, %2};" : "=l"(r) : "f"(lo), "f"(hi));
    return r;
}
DINL void upk2(unsigned long long v, float& lo, float& hi) {
    asm("mov.b64 {%0, %1}, %2;" : "=f"(lo), "=f"(hi) : "l"(v));
}
DINL void ffma2(unsigned long long& d, unsigned long long a, unsigned long long b) {
    asm("fma.rn.f32x2 %0, %1, %2, %0;" : "+l"(d) : "l"(a), "l"(b));
}

// ---------------- scratch ----------------

__device__ float g_x0[N_NODES * 92];
__device__ float g_xa[N_NODES * 256];
__device__ float g_xb[N_NODES * 256];
__device__ float g_agg[N_NODES * 256];
__device__ float g_sums[N_GRAPHS * 256];
__device__ float g_cnt[N_GRAPHS];
__device__ float g_h1[N_GRAPHS * 256];

// ---------------- kernels ----------------

__global__ void zero_k(float* __restrict__ p, int n) {
    for (int i = blockIdx.x * blockDim.x + threadIdx.x; i < n; i += gridDim.x * blockDim.x)
        p[i] = 0.f;
}

__global__ void embed_k(const int* __restrict__ xa, const float* __restrict__ emb,
                        float* __restrict__ x0) {
    int i = blockIdx.x * blockDim.x + threadIdx.x;
    if (i < N_NODES * 92) {
        int v = i / 92, c = i - v * 92;
        x0[i] = emb[xa[v] * 92 + c];
    }
}

// Fused edge conv: per edge e: h = softplus(ea@W1+b1); ee = h@W2+b2;
// msg = ee * x[src]; atomicAdd agg[dst] += msg.
// Tile TE edges per block; h staged in smem as h[k][e]; W2 staged in KC-row chunks.
template <int C, int KC, int TE, int BT>
__global__ __launch_bounds__(BT) void edge_conv_k(
    const float* __restrict__ x, const float* __restrict__ ea,
    const int* __restrict__ src, const int* __restrict__ dst,
    const float* __restrict__ w1, const float* __restrict__ b1,
    const float* __restrict__ w2, const float* __restrict__ b2,
    float* __restrict__ agg, int E) {
    extern __shared__ char smem[];
    float* hs = (float*)smem;            // [C][TE]
    float* ws = hs + C * TE;             // [KC][C]
    float* eas = ws + KC * C;            // [TE][5] (padded for bank-free reads)
    int* ss = (int*)(eas + TE * 5);      // [TE]
    int* ds = ss + TE;                   // [TE]

    const int tid = threadIdx.x;
    const int e0 = blockIdx.x * TE;

    for (int i = tid; i < TE; i += BT) {
        int eg = e0 + i;
        if (eg < E) {
            ss[i] = src[eg];
            ds[i] = dst[eg];
            float4 v = reinterpret_cast<const float4*>(ea)[eg];
            eas[i * 5 + 0] = v.x; eas[i * 5 + 1] = v.y;
            eas[i * 5 + 2] = v.z; eas[i * 5 + 3] = v.w;
        } else {
            ss[i] = -1; ds[i] = 0;
            eas[i * 5 + 0] = 0.f; eas[i * 5 + 1] = 0.f;
            eas[i * 5 + 2] = 0.f; eas[i * 5 + 3] = 0.f;
        }
    }
    __syncthreads();

    const int c = tid, lane = tid & 31;

    // Phase 1: hidden activations, thread c owns row c, staggered e -> conflict-free STS
    if (c < C) {
        float wa = w1[c], wb = w1[C + c], wc = w1[2 * C + c], wd = w1[3 * C + c];
        float bb = b1[c];
#pragma unroll 8
        for (int j = 0; j < TE; j++) {
            int e = (j + lane) & (TE - 1);
            float v = fmaf(eas[e * 5 + 0], wa,
                      fmaf(eas[e * 5 + 1], wb,
                      fmaf(eas[e * 5 + 2], wc,
                      fmaf(eas[e * 5 + 3], wd, bb))));
            hs[c * TE + e] = sp(v);
        }
    }

    // Phase 2: ee[e][c] = sum_k h[k][e] * W2[k][c] + b2[c], packed f32x2 over edge pairs
    unsigned long long acc[TE / 2];
    if (c < C) {
        float b2c = b2[c];
        unsigned long long ini = pk2(b2c, b2c);
#pragma unroll
        for (int j = 0; j < TE / 2; j++) acc[j] = ini;
    }
    for (int k0 = 0; k0 < C; k0 += KC) {
        __syncthreads();
        for (int i = tid; i < KC * C; i += BT) ws[i] = w2[k0 * C + i];
        __syncthreads();
        if (c < C) {
#pragma unroll 4
            for (int kk = 0; kk < KC; kk++) {
                float w = ws[kk * C + c];
                unsigned long long wp = pk2(w, w);
                const ulonglong2* hr =
                    reinterpret_cast<const ulonglong2*>(hs + (k0 + kk) * TE);
#pragma unroll
                for (int j = 0; j < TE / 4; j++) {
                    ulonglong2 q = hr[j];
                    ffma2(acc[2 * j], q.x, wp);
                    ffma2(acc[2 * j + 1], q.y, wp);
                }
            }
        }
    }

    // Epilogue: gather x[src], multiply, scatter-add to agg[dst]
    if (c < C) {
#pragma unroll
        for (int j = 0; j < TE / 2; j++) {
            float lo, hi;
            upk2(acc[j], lo, hi);
            int eA = 2 * j, eB = 2 * j + 1;
            int sA = ss[eA];
            if (sA >= 0)
                atomicAdd(agg + (size_t)ds[eA] * C + c, lo * __ldg(x + (size_t)sA * C + c));
            int sB = ss[eB];
            if (sB >= 0)
                atomicAdd(agg + (size_t)ds[eB] * C + c, hi * __ldg(x + (size_t)sB * C + c));
        }
    }
}

// Node update: y[v][j] = softplus( sum_k a[v][k] * W[k][j] + b[j] ), COUT = 256
template <int CIN, int KC, int TV, int BT>
__global__ __launch_bounds__(BT) void node_update_k(
    const float* __restrict__ a, const float* __restrict__ w,
    const float* __restrict__ b, float* __restrict__ y, int N) {
    extern __shared__ char smem[];
    float* as = (float*)smem;        // [CIN][TV]
    float* ws = as + CIN * TV;       // [KC][256]
    const int tid = threadIdx.x, lane = tid & 31;
    const int v0 = blockIdx.x * TV;

    if (tid < CIN) {
#pragma unroll 8
        for (int j = 0; j < TV; j++) {
            int v = (j + lane) & (TV - 1);
            as[tid * TV + v] = (v0 + v < N) ? a[(size_t)(v0 + v) * CIN + tid] : 0.f;
        }
    }

    float bc = b[tid];
    unsigned long long acc[TV / 2];
    {
        unsigned long long ini = pk2(bc, bc);
#pragma unroll
        for (int j = 0; j < TV / 2; j++) acc[j] = ini;
    }
    for (int k0 = 0; k0 < CIN; k0 += KC) {
        __syncthreads();
        for (int i = tid; i < KC * 256; i += BT) ws[i] = w[k0 * 256 + i];
        __syncthreads();
#pragma unroll 4
        for (int kk = 0; kk < KC; kk++) {
            float wv = ws[kk * 256 + tid];
            unsigned long long wp = pk2(wv, wv);
            const ulonglong2* ar =
                reinterpret_cast<const ulonglong2*>(as + (k0 + kk) * TV);
#pragma unroll
            for (int j = 0; j < TV / 4; j++) {
                ulonglong2 q = ar[j];
                ffma2(acc[2 * j], q.x, wp);
                ffma2(acc[2 * j + 1], q.y, wp);
            }
        }
    }
#pragma unroll
    for (int j = 0; j < TV / 2; j++) {
        float lo, hi;
        upk2(acc[j], lo, hi);
        int vA = v0 + 2 * j;
        if (vA < N) y[(size_t)vA * 256 + tid] = sp(lo);
        if (vA + 1 < N) y[(size_t)(vA + 1) * 256 + tid] = sp(hi);
    }
}

__global__ void count_k(const int* __restrict__ batch, float* __restrict__ cnt, int N) {
    int i = blockIdx.x * blockDim.x + threadIdx.x;
    if (i < N) atomicAdd(&cnt[batch[i]], 1.f);
}

// Mean-pool numerator: run-length compress consecutive same-graph nodes before atomics
__global__ void pool_k(const float* __restrict__ x, const int* __restrict__ batch,
                       float* __restrict__ sums, int N) {
    __shared__ int bs[32];
    int t = threadIdx.x;
    int v0 = blockIdx.x * 32;
    if (t < 32) bs[t] = (v0 + t < N) ? batch[v0 + t] : -1;
    __syncthreads();
    int cur = bs[0];
    if (cur < 0) return;
    float run = 0.f;
    for (int v = 0; v < 32; v++) {
        int bg = bs[v];
        if (bg < 0) break;
        if (bg != cur) {
            atomicAdd(&sums[cur * 256 + t], run);
            run = 0.f;
            cur = bg;
        }
        run += x[(size_t)(v0 + v) * 256 + t];
    }
    atomicAdd(&sums[cur * 256 + t], run);
}

__global__ void readout1_k(const float* __restrict__ sums, const float* __restrict__ cnt,
                           const float* __restrict__ rw1, const float* __restrict__ rb1,
                           float* __restrict__ h1) {
    __shared__ float gv[256];
    int g = blockIdx.x, t = threadIdx.x;
    float cn = fmaxf(cnt[g], 1.f);
    gv[t] = sums[g * 256 + t] / cn;
    __syncthreads();
    float acc = rb1[t];
#pragma unroll 8
    for (int k = 0; k < 256; k++) acc = fmaf(gv[k], rw1[k * 256 + t], acc);
    h1[g * 256 + t] = sp(acc);
}

__global__ void readout2_k(const float* __restrict__ h1, const float* __restrict__ rw2,
                           const float* __restrict__ rb2, const float* __restrict__ rw3,
                           const float* __restrict__ rb3, float* __restrict__ out) {
    __shared__ float hv[256];
    __shared__ float part[4];
    int g = blockIdx.x, t = threadIdx.x;  // 128 threads
    hv[t] = h1[g * 256 + t];
    hv[t + 128] = h1[g * 256 + 128 + t];
    __syncthreads();
    float acc = rb2[t];
#pragma unroll 8
    for (int k = 0; k < 256; k++) acc = fmaf(hv[k], rw2[k * 128 + t], acc);
    float p = sp(acc) * rw3[t];
#pragma unroll
    for (int o = 16; o; o >>= 1) p += __shfl_down_sync(0xFFFFFFFFu, p, o);
    if ((t & 31) == 0) part[t >> 5] = p;
    __syncthreads();
    if (t == 0) out[g] = part[0] + part[1] + part[2] + part[3] + rb3[0];
}

// ---------------- launch ----------------

static constexpr int SM_E256 = 256 * 64 * 4 + 32 * 256 * 4 + 64 * 5 * 4 + 64 * 8;  // 100096
static constexpr int SM_E92  = 92 * 64 * 4 + 23 * 92 * 4 + 64 * 5 * 4 + 64 * 8;    // 33808
static constexpr int SM_N256 = 256 * 64 * 4 + 32 * 256 * 4;                        // 98304
static constexpr int SM_N92  = 92 * 64 * 4 + 23 * 256 * 4;                         // 47104

extern "C" void kernel_launch(void* const* d_in, const int* in_sizes, int n_in,
                              void* d_out, int out_size) {
    const int* x_atoms = (const int*)d_in[0];
    const int* eidx    = (const int*)d_in[1];
    const float* eattr = (const float*)d_in[2];
    const int* batch   = (const int*)d_in[3];
    const float* emb   = (const float*)d_in[4];
    const float* ew1_0 = (const float*)d_in[5];
    const float* eb1_0 = (const float*)d_in[6];
    const float* ew2_0 = (const float*)d_in[7];
    const float* eb2_0 = (const float*)d_in[8];
    const float* nw_0  = (const float*)d_in[9];
    const float* nb_0  = (const float*)d_in[10];
    const float* ew1   = (const float*)d_in[11];
    const float* eb1   = (const float*)d_in[12];
    const float* ew2   = (const float*)d_in[13];
    const float* eb2   = (const float*)d_in[14];
    const float* nw    = (const float*)d_in[15];
    const float* nb    = (const float*)d_in[16];
    const float* rw1   = (const float*)d_in[17];
    const float* rb1   = (const float*)d_in[18];
    const float* rw2   = (const float*)d_in[19];
    const float* rb2   = (const float*)d_in[20];
    const float* rw3   = (const float*)d_in[21];
    const float* rb3   = (const float*)d_in[22];
    float* out = (float*)d_out;

    const int* src = eidx;
    const int* dst = eidx + N_EDGES;

    float *x0, *xa, *xb, *agg, *sums, *cnt, *h1;
    cudaGetSymbolAddress((void**)&x0, g_x0);
    cudaGetSymbolAddress((void**)&xa, g_xa);
    cudaGetSymbolAddress((void**)&xb, g_xb);
    cudaGetSymbolAddress((void**)&agg, g_agg);
    cudaGetSymbolAddress((void**)&sums, g_sums);
    cudaGetSymbolAddress((void**)&cnt, g_cnt);
    cudaGetSymbolAddress((void**)&h1, g_h1);

    cudaFuncSetAttribute(edge_conv_k<256, 32, 64, 256>,
                         cudaFuncAttributeMaxDynamicSharedMemorySize, SM_E256);
    cudaFuncSetAttribute(node_update_k<256, 32, 64, 256>,
                         cudaFuncAttributeMaxDynamicSharedMemorySize, SM_N256);
    cudaFuncSetAttribute(edge_conv_k<92, 23, 64, 128>,
                         cudaFuncAttributeMaxDynamicSharedMemorySize, SM_E92);
    cudaFuncSetAttribute(node_update_k<92, 23, 64, 256>,
                         cudaFuncAttributeMaxDynamicSharedMemorySize, SM_N92);

    const int EB = (N_EDGES + 63) / 64;   // 4688
    const int NB = (N_NODES + 63) / 64;   // 391

    // node embedding
    embed_k<<<(N_NODES * 92 + 255) / 256, 256>>>(x_atoms, emb, x0);

    // layer 0 (C=92 -> 256)
    zero_k<<<4096, 256>>>(agg, N_NODES * 92);
    edge_conv_k<92, 23, 64, 128><<<EB, 128, SM_E92>>>(
        x0, eattr, src, dst, ew1_0, eb1_0, ew2_0, eb2_0, agg, N_EDGES);
    node_update_k<92, 23, 64, 256><<<NB, 256, SM_N92>>>(agg, nw_0, nb_0, xa, N_NODES);

    // layers 1..3 (C=256)
    const float* xin = xa;
    float* xout = xb;
    for (int i = 0; i < 3; i++) {
        zero_k<<<8192, 256>>>(agg, N_NODES * 256);
        edge_conv_k<256, 32, 64, 256><<<EB, 256, SM_E256>>>(
            xin, eattr, src, dst,
            ew1 + i * 4 * 256, eb1 + i * 256,
            ew2 + i * 256 * 256, eb2 + i * 256, agg, N_EDGES);
        node_update_k<256, 32, 64, 256><<<NB, 256, SM_N256>>>(
            agg, nw + i * 256 * 256, nb + i * 256, xout, N_NODES);
        const float* t = xin;
        xin = xout;
        xout = (float*)t;
    }
    // final node features are in xin

    // pooling + readout
    zero_k<<<64, 256>>>(sums, N_GRAPHS * 256);
    zero_k<<<1, 256>>>(cnt, N_GRAPHS);
    count_k<<<(N_NODES + 255) / 256, 256>>>(batch, cnt, N_NODES);
    pool_k<<<(N_NODES + 31) / 32, 256>>>(xin, batch, sums, N_NODES);
    readout1_k<<<N_GRAPHS, 256>>>(sums, cnt, rw1, rb1, h1);
    readout2_k<<<N_GRAPHS, 128>>>(h1, rw2, rb2, rw3, rb3, out);
}

// round 3
// speedup vs baseline: 1.5749x; 1.5749x over previous
#include <cuda_runtime.h>

#define DINL __device__ __forceinline__
#define N_NODES 25000
#define N_EDGES 300000
#define N_GRAPHS 256

// ---------------- helpers ----------------

DINL float sp(float x) {
    return fmaxf(x, 0.f) + __logf(1.f + __expf(-fabsf(x)));
}
DINL unsigned long long pk2(float lo, float hi) {
    unsigned long long r;
    asm("mov.b64 %0, {%1, %2};" : "=l"(r) : "f"(lo), "f"(hi));
    return r;
}
DINL void upk2(unsigned long long v, float& lo, float& hi) {
    asm("mov.b64 {%0, %1}, %2;" : "=f"(lo), "=f"(hi) : "l"(v));
}
DINL void ffma2(unsigned long long& d, unsigned long long a, unsigned long long b) {
    asm("fma.rn.f32x2 %0, %1, %2, %0;" : "+l"(d) : "l"(a), "l"(b));
}
DINL void red4(float* a, float x, float y, float z, float w) {
    asm volatile("red.global.add.v4.f32 [%0], {%1, %2, %3, %4};"
                 :: "l"(a), "f"(x), "f"(y), "f"(z), "f"(w) : "memory");
}
// 64-float rows, 16B-chunk XOR swizzle (keeps 16B chunks intact)
DINL int swz(int k, int e) {
    return k * 64 + ((((e >> 2) ^ k) & 15) << 2) + (e & 3);
}

// ---------------- scratch ----------------

__device__ float g_x0[N_NODES * 128];     // layer-0 features, padded 92->128
__device__ float g_xa[N_NODES * 256];
__device__ float g_xb[N_NODES * 256];
__device__ float g_agg[N_NODES * 256];
__device__ float g_sums[N_GRAPHS * 256];
__device__ float g_cnt[N_GRAPHS];
__device__ float g_h1[N_GRAPHS * 256];

// ---------------- small kernels ----------------

__global__ void zero_k(float* __restrict__ p, int n) {
    for (int i = blockIdx.x * blockDim.x + threadIdx.x; i < n; i += gridDim.x * blockDim.x)
        p[i] = 0.f;
}

__global__ void embed_k(const int* __restrict__ xa, const float* __restrict__ emb,
                        float* __restrict__ x0) {
    int i = blockIdx.x * blockDim.x + threadIdx.x;
    if (i < N_NODES * 128) {
        int v = i >> 7, c = i & 127;
        x0[i] = (c < 92) ? emb[xa[v] * 92 + c] : 0.f;
    }
}

// ---------------- fused edge conv ----------------
// per edge: h = sp(ea@W1+b1) [C]; ee = h@W2+b2 [C]; red agg[dst] += ee * x[src]
// Tile: 64 edges x C outputs. Thread tile: 4 c x EPT edges. Warp lanes span c
// (h loads broadcast, weight LDS.128 conflict-free).
template <int C, int CR, int KC>
__global__ __launch_bounds__(256, 2) void edge_conv_k(
    const float* __restrict__ x, const float* __restrict__ ea,
    const int* __restrict__ src, const int* __restrict__ dst,
    const float* __restrict__ w1, const float* __restrict__ b1,
    const float* __restrict__ w2, const float* __restrict__ b2,
    float* __restrict__ agg, int E) {
    constexpr int TE = 64;
    constexpr int CT = C / 4;        // threads along c
    constexpr int ET = 256 / CT;     // edge groups
    constexpr int EPT = TE / ET;     // edges per thread
    constexpr int NP = EPT / 2;      // f32x2 pairs per channel

    extern __shared__ char smem[];
    float* hs  = (float*)smem;            // [C][64] swizzled
    float* ws  = hs + C * TE;             // [KC][C]
    float* ws1 = ws + KC * C;             // [5][C] (4 weights + bias)
    float* eas = ws1 + 5 * C;             // [64][5]
    int* ss = (int*)(eas + TE * 5);
    int* ds = ss + TE;

    const int tid = threadIdx.x;
    const int eblk = blockIdx.x * TE;

    // stage edge attrs + indices
    for (int i = tid; i < TE; i += 256) {
        int eg = eblk + i;
        if (eg < E) {
            ss[i] = src[eg];
            ds[i] = dst[eg];
            float4 v = reinterpret_cast<const float4*>(ea)[eg];
            eas[i * 5 + 0] = v.x; eas[i * 5 + 1] = v.y;
            eas[i * 5 + 2] = v.z; eas[i * 5 + 3] = v.w;
        } else {
            ss[i] = -1; ds[i] = 0;
            eas[i * 5 + 0] = 0.f; eas[i * 5 + 1] = 0.f;
            eas[i * 5 + 2] = 0.f; eas[i * 5 + 3] = 0.f;
        }
    }
    // stage W1/b1
    for (int i = tid; i < 5 * C; i += 256) {
        int m = i / C, k = i - m * C;
        float v = 0.f;
        if (k < CR) v = (m < 4) ? w1[m * CR + k] : b1[k];
        ws1[i] = v;
    }
    __syncthreads();

    // phase 1: hidden activations hs[k][e]
#pragma unroll 4
    for (int j = 0; j < C * TE / 256; j++) {
        int i = tid + j * 256;
        int k = i >> 6, e = i & 63;
        float v = fmaf(eas[e * 5 + 0], ws1[k],
                  fmaf(eas[e * 5 + 1], ws1[C + k],
                  fmaf(eas[e * 5 + 2], ws1[2 * C + k],
                  fmaf(eas[e * 5 + 3], ws1[3 * C + k], ws1[4 * C + k]))));
        hs[swz(k, e)] = sp(v);
    }

    // phase 2: ee = h @ W2 + b2, register-tiled
    const int ct = tid % CT;
    const int c0 = ct * 4;
    const int e0 = (tid / CT) * EPT;

    unsigned long long acc[4 * NP];
    {
        float4 bv = make_float4(0.f, 0.f, 0.f, 0.f);
        if (c0 < CR) bv = *(const float4*)(b2 + c0);
#pragma unroll
        for (int p = 0; p < NP; p++) {
            acc[0 * NP + p] = pk2(bv.x, bv.x);
            acc[1 * NP + p] = pk2(bv.y, bv.y);
            acc[2 * NP + p] = pk2(bv.z, bv.z);
            acc[3 * NP + p] = pk2(bv.w, bv.w);
        }
    }

    for (int k0 = 0; k0 < C; k0 += KC) {
        __syncthreads();
        if (CR == C) {
            const float4* g4 = (const float4*)(w2 + k0 * C);
            float4* s4 = (float4*)ws;
            for (int i = tid; i < KC * C / 4; i += 256) s4[i] = g4[i];
        } else {
            for (int i = tid; i < KC * C; i += 256) {
                int kk = i / C, c = i - kk * C;
                int k = k0 + kk;
                ws[i] = (k < CR && c < CR) ? w2[k * CR + c] : 0.f;
            }
        }
        __syncthreads();
#pragma unroll 2
        for (int kk = 0; kk < KC; kk++) {
            const int k = k0 + kk;
            float4 wv = *(const float4*)(ws + kk * C + c0);
            unsigned long long wp0 = pk2(wv.x, wv.x);
            unsigned long long wp1 = pk2(wv.y, wv.y);
            unsigned long long wp2 = pk2(wv.z, wv.z);
            unsigned long long wp3 = pk2(wv.w, wv.w);
            unsigned long long hp[NP];
#pragma unroll
            for (int ch = 0; ch < EPT / 4; ch++) {
                ulonglong2 q = *(const ulonglong2*)(hs + swz(k, e0 + ch * 4));
                hp[ch * 2] = q.x;
                hp[ch * 2 + 1] = q.y;
            }
#pragma unroll
            for (int p = 0; p < NP; p++) {
                ffma2(acc[0 * NP + p], hp[p], wp0);
                ffma2(acc[1 * NP + p], hp[p], wp1);
                ffma2(acc[2 * NP + p], hp[p], wp2);
                ffma2(acc[3 * NP + p], hp[p], wp3);
            }
        }
    }

    // epilogue: gather x[src], multiply, vector-red to agg[dst]
    if (c0 < CR) {
#pragma unroll
        for (int p = 0; p < NP; p++) {
            float a0, a1, a2, a3, q0, q1, q2, q3;
            upk2(acc[0 * NP + p], a0, q0);
            upk2(acc[1 * NP + p], a1, q1);
            upk2(acc[2 * NP + p], a2, q2);
            upk2(acc[3 * NP + p], a3, q3);
            int eA = e0 + 2 * p, eB = eA + 1;
            int sA = ss[eA];
            if (sA >= 0) {
                float4 xv = *(const float4*)(x + (size_t)sA * C + c0);
                red4(agg + (size_t)ds[eA] * C + c0,
                     a0 * xv.x, a1 * xv.y, a2 * xv.z, a3 * xv.w);
            }
            int sB = ss[eB];
            if (sB >= 0) {
                float4 xv = *(const float4*)(x + (size_t)sB * C + c0);
                red4(agg + (size_t)ds[eB] * C + c0,
                     q0 * xv.x, q1 * xv.y, q2 * xv.z, q3 * xv.w);
            }
        }
    }
}

// ---------------- node update: y = sp(a @ W + b), COUT=256 ----------------
template <int CIN, int CR, int KC>
__global__ __launch_bounds__(256, 2) void node_update_k(
    const float* __restrict__ a, const float* __restrict__ w,
    const float* __restrict__ b, float* __restrict__ y, int N) {
    constexpr int TV = 64;
    constexpr int CT = 64;           // 256 outputs / 4
    constexpr int EPT = 16;          // nodes per thread (4 groups)
    constexpr int NP = EPT / 2;

    extern __shared__ char smem[];
    float* as = (float*)smem;        // [CIN][64] swizzled (transposed stage)
    float* ws = as + CIN * TV;       // [KC][256]

    const int tid = threadIdx.x;
    const int v0 = blockIdx.x * TV;

    // transposed staging
    for (int j = 0; j < TV * CIN / 256; j++) {
        int i = tid + j * 256;
        int v = i / CIN, k = i - v * CIN;
        int vg = v0 + v;
        float val = (vg < N) ? a[(size_t)vg * CIN + k] : 0.f;
        as[swz(k, v)] = val;
    }

    const int c0 = (tid % CT) * 4;
    const int e0 = (tid / CT) * EPT;

    unsigned long long acc[4 * NP];
    {
        float4 bv = *(const float4*)(b + c0);
#pragma unroll
        for (int p = 0; p < NP; p++) {
            acc[0 * NP + p] = pk2(bv.x, bv.x);
            acc[1 * NP + p] = pk2(bv.y, bv.y);
            acc[2 * NP + p] = pk2(bv.z, bv.z);
            acc[3 * NP + p] = pk2(bv.w, bv.w);
        }
    }

    for (int k0 = 0; k0 < CIN; k0 += KC) {
        __syncthreads();
        if (CR == CIN) {
            const float4* g4 = (const float4*)(w + k0 * 256);
            float4* s4 = (float4*)ws;
            for (int i = tid; i < KC * 256 / 4; i += 256) s4[i] = g4[i];
        } else {
            for (int i = tid; i < KC * 256; i += 256) {
                int kk = i >> 8, c = i & 255;
                int k = k0 + kk;
                ws[i] = (k < CR) ? w[k * 256 + c] : 0.f;
            }
        }
        __syncthreads();
#pragma unroll 2
        for (int kk = 0; kk < KC; kk++) {
            const int k = k0 + kk;
            float4 wv = *(const float4*)(ws + kk * 256 + c0);
            unsigned long long wp0 = pk2(wv.x, wv.x);
            unsigned long long wp1 = pk2(wv.y, wv.y);
            unsigned long long wp2 = pk2(wv.z, wv.z);
            unsigned long long wp3 = pk2(wv.w, wv.w);
            unsigned long long hp[NP];
#pragma unroll
            for (int ch = 0; ch < EPT / 4; ch++) {
                ulonglong2 q = *(const ulonglong2*)(as + swz(k, e0 + ch * 4));
                hp[ch * 2] = q.x;
                hp[ch * 2 + 1] = q.y;
            }
#pragma unroll
            for (int p = 0; p < NP; p++) {
                ffma2(acc[0 * NP + p], hp[p], wp0);
                ffma2(acc[1 * NP + p], hp[p], wp1);
                ffma2(acc[2 * NP + p], hp[p], wp2);
                ffma2(acc[3 * NP + p], hp[p], wp3);
            }
        }
    }

#pragma unroll
    for (int p = 0; p < NP; p++) {
        float a0, a1, a2, a3, q0, q1, q2, q3;
        upk2(acc[0 * NP + p], a0, q0);
        upk2(acc[1 * NP + p], a1, q1);
        upk2(acc[2 * NP + p], a2, q2);
        upk2(acc[3 * NP + p], a3, q3);
        int vA = v0 + e0 + 2 * p;
        if (vA < N)
            *(float4*)(y + (size_t)vA * 256 + c0) =
                make_float4(sp(a0), sp(a1), sp(a2), sp(a3));
        if (vA + 1 < N)
            *(float4*)(y + (size_t)(vA + 1) * 256 + c0) =
                make_float4(sp(q0), sp(q1), sp(q2), sp(q3));
    }
}

// ---------------- pooling / readout ----------------

__global__ void count_k(const int* __restrict__ batch, float* __restrict__ cnt, int N) {
    int i = blockIdx.x * blockDim.x + threadIdx.x;
    if (i < N) atomicAdd(&cnt[batch[i]], 1.f);
}

__global__ void pool_k(const float* __restrict__ x, const int* __restrict__ batch,
                       float* __restrict__ sums, int N) {
    __shared__ int bs[32];
    int t = threadIdx.x;
    int v0 = blockIdx.x * 32;
    if (t < 32) bs[t] = (v0 + t < N) ? batch[v0 + t] : -1;
    __syncthreads();
    int cur = bs[0];
    if (cur < 0) return;
    float run = 0.f;
    for (int v = 0; v < 32; v++) {
        int bg = bs[v];
        if (bg < 0) break;
        if (bg != cur) {
            atomicAdd(&sums[cur * 256 + t], run);
            run = 0.f;
            cur = bg;
        }
        run += x[(size_t)(v0 + v) * 256 + t];
    }
    atomicAdd(&sums[cur * 256 + t], run);
}

__global__ void readout1_k(const float* __restrict__ sums, const float* __restrict__ cnt,
                           const float* __restrict__ rw1, const float* __restrict__ rb1,
                           float* __restrict__ h1) {
    __shared__ float gv[256];
    int g = blockIdx.x, t = threadIdx.x;
    float cn = fmaxf(cnt[g], 1.f);
    gv[t] = sums[g * 256 + t] / cn;
    __syncthreads();
    float acc = rb1[t];
#pragma unroll 8
    for (int k = 0; k < 256; k++) acc = fmaf(gv[k], rw1[k * 256 + t], acc);
    h1[g * 256 + t] = sp(acc);
}

__global__ void readout2_k(const float* __restrict__ h1, const float* __restrict__ rw2,
                           const float* __restrict__ rb2, const float* __restrict__ rw3,
                           const float* __restrict__ rb3, float* __restrict__ out) {
    __shared__ float hv[256];
    __shared__ float part[4];
    int g = blockIdx.x, t = threadIdx.x;  // 128 threads
    hv[t] = h1[g * 256 + t];
    hv[t + 128] = h1[g * 256 + 128 + t];
    __syncthreads();
    float acc = rb2[t];
#pragma unroll 8
    for (int k = 0; k < 256; k++) acc = fmaf(hv[k], rw2[k * 128 + t], acc);
    float p = sp(acc) * rw3[t];
#pragma unroll
    for (int o = 16; o; o >>= 1) p += __shfl_down_sync(0xFFFFFFFFu, p, o);
    if ((t & 31) == 0) part[t >> 5] = p;
    __syncthreads();
    if (t == 0) out[g] = part[0] + part[1] + part[2] + part[3] + rb3[0];
}

// ---------------- launch ----------------

static constexpr int SM_E256 = 256 * 64 * 4 + 32 * 256 * 4 + 5 * 256 * 4 + 64 * 5 * 4 + 64 * 8;  // 105216
static constexpr int SM_E128 = 128 * 64 * 4 + 32 * 128 * 4 + 5 * 128 * 4 + 64 * 5 * 4 + 64 * 8;  // 53504
static constexpr int SM_N256 = 256 * 64 * 4 + 32 * 256 * 4;  // 98304
static constexpr int SM_N128 = 128 * 64 * 4 + 32 * 256 * 4;  // 65536

extern "C" void kernel_launch(void* const* d_in, const int* in_sizes, int n_in,
                              void* d_out, int out_size) {
    const int* x_atoms = (const int*)d_in[0];
    const int* eidx    = (const int*)d_in[1];
    const float* eattr = (const float*)d_in[2];
    const int* batch   = (const int*)d_in[3];
    const float* emb   = (const float*)d_in[4];
    const float* ew1_0 = (const float*)d_in[5];
    const float* eb1_0 = (const float*)d_in[6];
    const float* ew2_0 = (const float*)d_in[7];
    const float* eb2_0 = (const float*)d_in[8];
    const float* nw_0  = (const float*)d_in[9];
    const float* nb_0  = (const float*)d_in[10];
    const float* ew1   = (const float*)d_in[11];
    const float* eb1   = (const float*)d_in[12];
    const float* ew2   = (const float*)d_in[13];
    const float* eb2   = (const float*)d_in[14];
    const float* nw    = (const float*)d_in[15];
    const float* nb    = (const float*)d_in[16];
    const float* rw1   = (const float*)d_in[17];
    const float* rb1   = (const float*)d_in[18];
    const float* rw2   = (const float*)d_in[19];
    const float* rb2   = (const float*)d_in[20];
    const float* rw3   = (const float*)d_in[21];
    const float* rb3   = (const float*)d_in[22];
    float* out = (float*)d_out;

    const int* src = eidx;
    const int* dst = eidx + N_EDGES;

    float *x0, *xa, *xb, *agg, *sums, *cnt, *h1;
    cudaGetSymbolAddress((void**)&x0, g_x0);
    cudaGetSymbolAddress((void**)&xa, g_xa);
    cudaGetSymbolAddress((void**)&xb, g_xb);
    cudaGetSymbolAddress((void**)&agg, g_agg);
    cudaGetSymbolAddress((void**)&sums, g_sums);
    cudaGetSymbolAddress((void**)&cnt, g_cnt);
    cudaGetSymbolAddress((void**)&h1, g_h1);

    cudaFuncSetAttribute(edge_conv_k<256, 256, 32>,
                         cudaFuncAttributeMaxDynamicSharedMemorySize, SM_E256);
    cudaFuncSetAttribute(edge_conv_k<128, 92, 32>,
                         cudaFuncAttributeMaxDynamicSharedMemorySize, SM_E128);
    cudaFuncSetAttribute(node_update_k<256, 256, 32>,
                         cudaFuncAttributeMaxDynamicSharedMemorySize, SM_N256);
    cudaFuncSetAttribute(node_update_k<128, 92, 32>,
                         cudaFuncAttributeMaxDynamicSharedMemorySize, SM_N128);

    const int EB = (N_EDGES + 63) / 64;   // 4688
    const int NB = (N_NODES + 63) / 64;   // 391

    embed_k<<<(N_NODES * 128 + 255) / 256, 256>>>(x_atoms, emb, x0);

    // layer 0 (92 padded to 128)
    zero_k<<<4096, 256>>>(agg, N_NODES * 128);
    edge_conv_k<128, 92, 32><<<EB, 256, SM_E128>>>(
        x0, eattr, src, dst, ew1_0, eb1_0, ew2_0, eb2_0, agg, N_EDGES);
    node_update_k<128, 92, 32><<<NB, 256, SM_N128>>>(agg, nw_0, nb_0, xa, N_NODES);

    // layers 1..3
    const float* xin = xa;
    float* xout = xb;
    for (int i = 0; i < 3; i++) {
        zero_k<<<8192, 256>>>(agg, N_NODES * 256);
        edge_conv_k<256, 256, 32><<<EB, 256, SM_E256>>>(
            xin, eattr, src, dst,
            ew1 + i * 4 * 256, eb1 + i * 256,
            ew2 + i * 256 * 256, eb2 + i * 256, agg, N_EDGES);
        node_update_k<256, 256, 32><<<NB, 256, SM_N256>>>(
            agg, nw + i * 256 * 256, nb + i * 256, xout, N_NODES);
        const float* t = xin;
        xin = xout;
        xout = (float*)t;
    }

    // pooling + readout
    zero_k<<<64, 256>>>(sums, N_GRAPHS * 256);
    zero_k<<<1, 256>>>(cnt, N_GRAPHS);
    count_k<<<(N_NODES + 255) / 256, 256>>>(batch, cnt, N_NODES);
    pool_k<<<(N_NODES + 31) / 32, 256>>>(xin, batch, sums, N_NODES);
    readout1_k<<<N_GRAPHS, 256>>>(sums, cnt, rw1, rb1, h1);
    readout2_k<<<N_GRAPHS, 128>>>(h1, rw2, rb2, rw3, rb3, out);
}

// round 8
// speedup vs baseline: 4.6538x; 2.9550x over previous
#include <cuda_runtime.h>
#include <cuda_fp16.h>
#include <cstdint>

#define DINL __device__ __forceinline__
#define N_NODES 25000
#define N_EDGES 300000
#define N_GRAPHS 256

// ---------------- helpers ----------------

DINL uint32_t smem_u32(const void* p) {
    uint32_t a;
    asm("{ .reg .u64 t; cvta.to.shared.u64 t, %1; cvt.u32.u64 %0, t; }" : "=r"(a) : "l"(p));
    return a;
}
DINL float sp(float x) {
    return fmaxf(x, 0.f) + __logf(1.f + __expf(-fabsf(x)));
}
DINL void red4(float* a, float x, float y, float z, float w) {
    asm volatile("red.global.add.v4.f32 [%0], {%1, %2, %3, %4};"
                 :: "l"(a), "f"(x), "f"(y), "f"(z), "f"(w) : "memory");
}
DINL uint32_t pkhf(float lo, float hi) {
    uint32_t u;
    asm("cvt.rn.f16x2.f32 %0, %1, %2;" : "=r"(u) : "f"(hi), "f"(lo));
    return u;
}
DINL void ldsm4(uint32_t& r0, uint32_t& r1, uint32_t& r2, uint32_t& r3, uint32_t a) {
    asm volatile("ldmatrix.sync.aligned.m8n8.x4.shared.b16 {%0,%1,%2,%3}, [%4];"
                 : "=r"(r0), "=r"(r1), "=r"(r2), "=r"(r3) : "r"(a));
}
DINL void mma_f16(float* d, const uint32_t* a, const uint32_t* b) {
    asm volatile("mma.sync.aligned.m16n8k16.row.col.f32.f16.f16.f32 "
                 "{%0,%1,%2,%3}, {%4,%5,%6,%7}, {%8,%9}, {%0,%1,%2,%3};"
                 : "+f"(d[0]), "+f"(d[1]), "+f"(d[2]), "+f"(d[3])
                 : "r"(a[0]), "r"(a[1]), "r"(a[2]), "r"(a[3]), "r"(b[0]), "r"(b[1]));
}
// K-major SW128 blocked-atom byte offset (swizzle affects only k-byte bits 4..6)
DINL int imgoff(int r, int k, int nra) {
    int base = ((r >> 3) + (k >> 6) * nra) * 1024 + (r & 7) * 128;
    int kb = ((k & 63) << 1) ^ ((r & 7) << 4);
    return base + kb;
}
// fragment-column -> actual-channel permutation (so each thread covers 4 contiguous chans)
DINL int chan(int p) {
    int q = p & 15;
    int cl = (q < 8) ? (((q >> 1) << 2) | (q & 1))
                     : ((((q - 8) >> 1) << 2) | 2 | (q & 1));
    return (p & ~15) | cl;
}

// ---------------- scratch ----------------

__device__ float g_x0[N_NODES * 128];
__device__ float g_xa[N_NODES * 256];
__device__ float g_xb[N_NODES * 256];
__device__ float g_agg[N_NODES * 256];
__device__ float g_sums[N_GRAPHS * 256];
__device__ float g_cnt[N_GRAPHS];
__device__ float g_h1[N_GRAPHS * 256];
__device__ __half g_imgE0[128 * 128];
__device__ __half g_imgE[3 * 256 * 256];
__device__ __half g_imgN0[256 * 128];
__device__ __half g_imgN[3 * 256 * 256];

// ---------------- small kernels ----------------

__global__ void zero_k(float* __restrict__ p, int n) {
    for (int i = blockIdx.x * blockDim.x + threadIdx.x; i < n; i += gridDim.x * blockDim.x)
        p[i] = 0.f;
}

__global__ void embed_k(const int* __restrict__ xa, const float* __restrict__ emb,
                        float* __restrict__ x0) {
    int i = blockIdx.x * blockDim.x + threadIdx.x;
    if (i < N_NODES * 128) {
        int v = i >> 7, c = i & 127;
        x0[i] = (c < 92) ? emb[xa[v] * 92 + c] : 0.f;
    }
}

// Weight image: img[p][k] = W[k][chan(p)] (transposed + col-permuted + swizzled fp16)
__global__ void prep_img_k(const float* __restrict__ w, __half* __restrict__ img,
                           int K, int N, int CRk, int CRn) {
    int i = blockIdx.x * blockDim.x + threadIdx.x;
    if (i >= N * K) return;
    int p = i / K, k = i - p * K;
    int c = chan(p);
    float v = (k < CRk && c < CRn) ? w[k * CRn + c] : 0.f;
    *(__half*)((char*)img + imgoff(p, k, N >> 3)) = __float2half(v);
}

// ---------------- fused HMMA tile kernel ----------------
// EDGE: A = f16(softplus(ea@W1+b1)) [128,K]; D = A@Bimg^T [128,N];
//       red agg[dst] += (D + b2) * x[src]
// NODE: A = f16(rows of a); D = A@Bimg^T; y = softplus(D + b)  (out width 256)
template <int K, int N, bool EDGE>
__global__ __launch_bounds__(256, 1)
void gemm_tile_k(const float* __restrict__ xs, const float* __restrict__ ea,
                 const int* __restrict__ src, const int* __restrict__ dst,
                 const float* __restrict__ w1, const float* __restrict__ b1,
                 const __half* __restrict__ bimg,
                 const float* __restrict__ bias, int CRb,
                 float* __restrict__ outp, int count) {
    constexpr int A_BYTES = 128 * K * 2;
    constexpr int B_BYTES = N * K * 2;
    constexpr int ASTR = 16 * 1024;        // A stride per 64-k block (128 rows)
    constexpr int BSTR = (N / 8) * 1024;   // B stride per 64-k block

    extern __shared__ char smem[];
    char* As = smem;
    char* Bs = smem + A_BYTES;
    float* ws1 = (float*)(Bs + B_BYTES);   // [5][K]
    float* biass = ws1 + 5 * K;            // [N]
    float* eas = biass + N;                // [128][5]
    int* ss = (int*)(eas + 128 * 5);
    int* ds = ss + 128;

    const int tid = threadIdx.x;
    const int lane = tid & 31;
    const int warp = tid >> 5;

    // ---- staging ----
    if (EDGE) {
        for (int i = tid; i < 128; i += 256) {
            int eg = blockIdx.x * 128 + i;
            if (eg < count) {
                ss[i] = src[eg];
                ds[i] = dst[eg];
                float4 v = reinterpret_cast<const float4*>(ea)[eg];
                eas[i * 5 + 0] = v.x; eas[i * 5 + 1] = v.y;
                eas[i * 5 + 2] = v.z; eas[i * 5 + 3] = v.w;
            } else {
                ss[i] = -1; ds[i] = 0;
                eas[i * 5 + 0] = 0.f; eas[i * 5 + 1] = 0.f;
                eas[i * 5 + 2] = 0.f; eas[i * 5 + 3] = 0.f;
            }
        }
        for (int i = tid; i < 5 * K; i += 256) {
            int m = i / K, k = i - m * K;
            ws1[i] = (k < CRb) ? ((m < 4) ? w1[m * CRb + k] : b1[k]) : 0.f;
        }
    }
    for (int i = tid; i < N; i += 256) biass[i] = (i < CRb) ? bias[i] : 0.f;
    {
        const float4* g = (const float4*)bimg;
        float4* s = (float4*)Bs;
        for (int i = tid; i < B_BYTES / 16; i += 256) s[i] = g[i];
    }
    __syncthreads();

    // ---- phase 1: build f16 A tile (swizzled) ----
    if (EDGE) {
        constexpr int PAIRS = K / 2;
        constexpr int EG = 256 / PAIRS;
        const int k = (tid & (PAIRS - 1)) * 2;
        const int grp = tid / PAIRS;
        float wa0 = ws1[k],         wa1 = ws1[k + 1];
        float wb0 = ws1[K + k],     wb1 = ws1[K + k + 1];
        float wc0 = ws1[2 * K + k], wc1 = ws1[2 * K + k + 1];
        float wd0 = ws1[3 * K + k], wd1 = ws1[3 * K + k + 1];
        float bb0 = ws1[4 * K + k], bb1 = ws1[4 * K + k + 1];
#pragma unroll 4
        for (int e = grp; e < 128; e += EG) {
            float a0 = eas[e * 5 + 0], a1 = eas[e * 5 + 1];
            float a2 = eas[e * 5 + 2], a3 = eas[e * 5 + 3];
            float z0 = fmaf(a0, wa0, fmaf(a1, wb0, fmaf(a2, wc0, fmaf(a3, wd0, bb0))));
            float z1 = fmaf(a0, wa1, fmaf(a1, wb1, fmaf(a2, wc1, fmaf(a3, wd1, bb1))));
            *(uint32_t*)(As + imgoff(e, k, 16)) = pkhf(sp(z0), sp(z1));
        }
    } else {
        constexpr int KT = K / 4;
        constexpr int VG = 256 / KT;
        const int k4 = (tid % KT) * 4;
        const int vg = tid / KT;
        const int v0 = blockIdx.x * 128;
#pragma unroll 4
        for (int v = vg; v < 128; v += VG) {
            int gv = v0 + v;
            float4 av = (gv < count)
                ? __ldg((const float4*)(xs + (size_t)gv * K + k4))
                : make_float4(0.f, 0.f, 0.f, 0.f);
            int off = imgoff(v, k4, 16);
            *(uint32_t*)(As + off) = pkhf(av.x, av.y);
            *(uint32_t*)(As + off + 4) = pkhf(av.z, av.w);
        }
    }
    __syncthreads();

    // ---- HMMA ----
    const uint32_t smbA = smem_u32(As);
    const uint32_t smbB = smem_u32(Bs);
    const int wm = warp & 1, wn = warp >> 1;
    const int m0 = wm * 64;
    const int lr = lane & 7, lg = lane >> 3;
    const uint32_t sw = (uint32_t)(lr << 4);
    const int kofA = (lg >> 1) * 8;   // A: groups 2,3 -> k+8
    const int kofB = (lg & 1) * 8;    // B: groups 1,3 -> k+8

    uint32_t abase[4];
#pragma unroll
    for (int mi = 0; mi < 4; mi++)
        abase[mi] = smbA + (uint32_t)((wm * 8 + mi * 2 + (lg & 1)) * 1024 + lr * 128);

    const int tq = lane >> 2, tr = lane & 3;

#pragma unroll
    for (int np = 0; np < N / 128; np++) {
        float acc[4][4][4];
#pragma unroll
        for (int mi = 0; mi < 4; mi++)
#pragma unroll
            for (int ni = 0; ni < 4; ni++)
#pragma unroll
                for (int q = 0; q < 4; q++) acc[mi][ni][q] = 0.f;

        // B lane bases: x4 #0 covers n-tiles 0,1 ; x4 #1 covers n-tiles 2,3
        uint32_t bb0 = smbB + (uint32_t)(((np * 16 + wn * 4 + (lg >> 1)) * 1024) + lr * 128);
        uint32_t bb1 = bb0 + 2 * 1024;

#pragma unroll 2
        for (int k0 = 0; k0 < K; k0 += 16) {
            uint32_t blk = (uint32_t)(k0 >> 6);
            uint32_t kbA = (uint32_t)((((k0 & 63) + kofA) << 1)) ^ sw;
            uint32_t kbB = (uint32_t)((((k0 & 63) + kofB) << 1)) ^ sw;
            uint32_t akadd = blk * ASTR + kbA;
            uint32_t bkadd = blk * BSTR + kbB;

            uint32_t af[4][4];
#pragma unroll
            for (int mi = 0; mi < 4; mi++)
                ldsm4(af[mi][0], af[mi][1], af[mi][2], af[mi][3], abase[mi] + akadd);
            uint32_t b01[4], b23[4];
            ldsm4(b01[0], b01[1], b01[2], b01[3], bb0 + bkadd);
            ldsm4(b23[0], b23[1], b23[2], b23[3], bb1 + bkadd);

#pragma unroll
            for (int mi = 0; mi < 4; mi++) {
                mma_f16(acc[mi][0], af[mi], b01 + 0);
                mma_f16(acc[mi][1], af[mi], b01 + 2);
                mma_f16(acc[mi][2], af[mi], b23 + 0);
                mma_f16(acc[mi][3], af[mi], b23 + 2);
            }
        }

        // ---- epilogue straight from fragments ----
        const int nb = np * 128 + wn * 32;
        if (EDGE) {
#pragma unroll
            for (int mi = 0; mi < 4; mi++) {
#pragma unroll
                for (int hf = 0; hf < 2; hf++) {
                    int row = m0 + mi * 16 + tq + hf * 8;
                    int s = ss[row];
                    if (s < 0) continue;
                    const float* xrow = xs + (size_t)s * N;
                    float* arow = outp + (size_t)ds[row] * N;
#pragma unroll
                    for (int p = 0; p < 2; p++) {
                        int c0 = nb + p * 16 + tr * 4;
                        float4 bv = *(const float4*)(biass + c0);
                        float4 xv = __ldg((const float4*)(xrow + c0));
                        float v0 = acc[mi][2 * p][2 * hf],     v1 = acc[mi][2 * p][2 * hf + 1];
                        float v2 = acc[mi][2 * p + 1][2 * hf], v3 = acc[mi][2 * p + 1][2 * hf + 1];
                        red4(arow + c0, (v0 + bv.x) * xv.x, (v1 + bv.y) * xv.y,
                             (v2 + bv.z) * xv.z, (v3 + bv.w) * xv.w);
                    }
                }
            }
        } else {
            const int v0b = blockIdx.x * 128;
#pragma unroll
            for (int mi = 0; mi < 4; mi++) {
#pragma unroll
                for (int hf = 0; hf < 2; hf++) {
                    int row = m0 + mi * 16 + tq + hf * 8;
                    int gv = v0b + row;
                    if (gv >= count) continue;
                    float* yrow = outp + (size_t)gv * 256;
#pragma unroll
                    for (int p = 0; p < 2; p++) {
                        int c0 = nb + p * 16 + tr * 4;
                        float4 bv = *(const float4*)(biass + c0);
                        float v0 = acc[mi][2 * p][2 * hf],     v1 = acc[mi][2 * p][2 * hf + 1];
                        float v2 = acc[mi][2 * p + 1][2 * hf], v3 = acc[mi][2 * p + 1][2 * hf + 1];
                        *(float4*)(yrow + c0) = make_float4(
                            sp(v0 + bv.x), sp(v1 + bv.y), sp(v2 + bv.z), sp(v3 + bv.w));
                    }
                }
            }
        }
    }
}

// ---------------- pooling / readout ----------------

__global__ void count_k(const int* __restrict__ batch, float* __restrict__ cnt, int N) {
    int i = blockIdx.x * blockDim.x + threadIdx.x;
    if (i < N) atomicAdd(&cnt[batch[i]], 1.f);
}

__global__ void pool_k(const float* __restrict__ x, const int* __restrict__ batch,
                       float* __restrict__ sums, int N) {
    __shared__ int bs[32];
    int t = threadIdx.x;
    int v0 = blockIdx.x * 32;
    if (t < 32) bs[t] = (v0 + t < N) ? batch[v0 + t] : -1;
    __syncthreads();
    int cur = bs[0];
    if (cur < 0) return;
    float run = 0.f;
    for (int v = 0; v < 32; v++) {
        int bg = bs[v];
        if (bg < 0) break;
        if (bg != cur) {
            atomicAdd(&sums[cur * 256 + t], run);
            run = 0.f;
            cur = bg;
        }
        run += x[(size_t)(v0 + v) * 256 + t];
    }
    atomicAdd(&sums[cur * 256 + t], run);
}

__global__ void readout1_k(const float* __restrict__ sums, const float* __restrict__ cnt,
                           const float* __restrict__ rw1, const float* __restrict__ rb1,
                           float* __restrict__ h1) {
    __shared__ float gv[256];
    int g = blockIdx.x, t = threadIdx.x;
    float cn = fmaxf(cnt[g], 1.f);
    gv[t] = sums[g * 256 + t] / cn;
    __syncthreads();
    float acc = rb1[t];
#pragma unroll 8
    for (int k = 0; k < 256; k++) acc = fmaf(gv[k], rw1[k * 256 + t], acc);
    h1[g * 256 + t] = sp(acc);
}

__global__ void readout2_k(const float* __restrict__ h1, const float* __restrict__ rw2,
                           const float* __restrict__ rb2, const float* __restrict__ rw3,
                           const float* __restrict__ rb3, float* __restrict__ out) {
    __shared__ float hv[256];
    __shared__ float part[4];
    int g = blockIdx.x, t = threadIdx.x;  // 128 threads
    hv[t] = h1[g * 256 + t];
    hv[t + 128] = h1[g * 256 + 128 + t];
    __syncthreads();
    float acc = rb2[t];
#pragma unroll 8
    for (int k = 0; k < 256; k++) acc = fmaf(hv[k], rw2[k * 128 + t], acc);
    float p = sp(acc) * rw3[t];
#pragma unroll
    for (int o = 16; o; o >>= 1) p += __shfl_down_sync(0xFFFFFFFFu, p, o);
    if ((t & 31) == 0) part[t >> 5] = p;
    __syncthreads();
    if (t == 0) out[g] = part[0] + part[1] + part[2] + part[3] + rb3[0];
}

// ---------------- launch ----------------

static constexpr int smem_sz(int K, int N) {
    return 128 * K * 2 + N * K * 2 + (5 * K + N + 128 * 5 + 256) * 4 + 64;
}

extern "C" void kernel_launch(void* const* d_in, const int* in_sizes, int n_in,
                              void* d_out, int out_size) {
    const int* x_atoms = (const int*)d_in[0];
    const int* eidx    = (const int*)d_in[1];
    const float* eattr = (const float*)d_in[2];
    const int* batch   = (const int*)d_in[3];
    const float* emb   = (const float*)d_in[4];
    const float* ew1_0 = (const float*)d_in[5];
    const float* eb1_0 = (const float*)d_in[6];
    const float* ew2_0 = (const float*)d_in[7];
    const float* eb2_0 = (const float*)d_in[8];
    const float* nw_0  = (const float*)d_in[9];
    const float* nb_0  = (const float*)d_in[10];
    const float* ew1   = (const float*)d_in[11];
    const float* eb1   = (const float*)d_in[12];
    const float* ew2   = (const float*)d_in[13];
    const float* eb2   = (const float*)d_in[14];
    const float* nw    = (const float*)d_in[15];
    const float* nb    = (const float*)d_in[16];
    const float* rw1   = (const float*)d_in[17];
    const float* rb1   = (const float*)d_in[18];
    const float* rw2   = (const float*)d_in[19];
    const float* rb2   = (const float*)d_in[20];
    const float* rw3   = (const float*)d_in[21];
    const float* rb3   = (const float*)d_in[22];
    float* out = (float*)d_out;

    const int* src = eidx;
    const int* dst = eidx + N_EDGES;

    float *x0, *xa, *xb, *agg, *sums, *cnt, *h1;
    __half *imgE0, *imgE, *imgN0, *imgN;
    cudaGetSymbolAddress((void**)&x0, g_x0);
    cudaGetSymbolAddress((void**)&xa, g_xa);
    cudaGetSymbolAddress((void**)&xb, g_xb);
    cudaGetSymbolAddress((void**)&agg, g_agg);
    cudaGetSymbolAddress((void**)&sums, g_sums);
    cudaGetSymbolAddress((void**)&cnt, g_cnt);
    cudaGetSymbolAddress((void**)&h1, g_h1);
    cudaGetSymbolAddress((void**)&imgE0, g_imgE0);
    cudaGetSymbolAddress((void**)&imgE, g_imgE);
    cudaGetSymbolAddress((void**)&imgN0, g_imgN0);
    cudaGetSymbolAddress((void**)&imgN, g_imgN);

    cudaFuncSetAttribute(gemm_tile_k<256, 256, true>,
                         cudaFuncAttributeMaxDynamicSharedMemorySize, smem_sz(256, 256));
    cudaFuncSetAttribute(gemm_tile_k<128, 128, true>,
                         cudaFuncAttributeMaxDynamicSharedMemorySize, smem_sz(128, 128));
    cudaFuncSetAttribute(gemm_tile_k<256, 256, false>,
                         cudaFuncAttributeMaxDynamicSharedMemorySize, smem_sz(256, 256));
    cudaFuncSetAttribute(gemm_tile_k<128, 256, false>,
                         cudaFuncAttributeMaxDynamicSharedMemorySize, smem_sz(128, 256));

    // weight images (transposed + col-permuted + swizzled fp16)
    prep_img_k<<<(128 * 128 + 255) / 256, 256>>>(ew2_0, imgE0, 128, 128, 92, 92);
    prep_img_k<<<(256 * 128 + 255) / 256, 256>>>(nw_0, imgN0, 128, 256, 92, 256);
    for (int i = 0; i < 3; i++) {
        prep_img_k<<<(256 * 256 + 255) / 256, 256>>>(ew2 + i * 65536, imgE + i * 65536,
                                                     256, 256, 256, 256);
        prep_img_k<<<(256 * 256 + 255) / 256, 256>>>(nw + i * 65536, imgN + i * 65536,
                                                     256, 256, 256, 256);
    }

    embed_k<<<(N_NODES * 128 + 255) / 256, 256>>>(x_atoms, emb, x0);

    const int EB = (N_EDGES + 127) / 128;   // 2344
    const int NB = (N_NODES + 127) / 128;   // 196

    // layer 0 (92 padded to 128)
    zero_k<<<4096, 256>>>(agg, N_NODES * 128);
    gemm_tile_k<128, 128, true><<<EB, 256, smem_sz(128, 128)>>>(
        x0, eattr, src, dst, ew1_0, eb1_0, imgE0, eb2_0, 92, agg, N_EDGES);
    gemm_tile_k<128, 256, false><<<NB, 256, smem_sz(128, 256)>>>(
        agg, nullptr, nullptr, nullptr, nullptr, nullptr, imgN0, nb_0, 256, xa, N_NODES);

    // layers 1..3
    const float* xin = xa;
    float* xout = xb;
    for (int i = 0; i < 3; i++) {
        zero_k<<<8192, 256>>>(agg, N_NODES * 256);
        gemm_tile_k<256, 256, true><<<EB, 256, smem_sz(256, 256)>>>(
            xin, eattr, src, dst, ew1 + i * 4 * 256, eb1 + i * 256,
            imgE + i * 65536, eb2 + i * 256, 256, agg, N_EDGES);
        gemm_tile_k<256, 256, false><<<NB, 256, smem_sz(256, 256)>>>(
            agg, nullptr, nullptr, nullptr, nullptr, nullptr,
            imgN + i * 65536, nb + i * 256, 256, xout, N_NODES);
        const float* t = xin;
        xin = xout;
        xout = (float*)t;
    }

    // pooling + readout
    zero_k<<<64, 256>>>(sums, N_GRAPHS * 256);
    zero_k<<<1, 256>>>(cnt, N_GRAPHS);
    count_k<<<(N_NODES + 255) / 256, 256>>>(batch, cnt, N_NODES);
    pool_k<<<(N_NODES + 31) / 32, 256>>>(xin, batch, sums, N_NODES);
    readout1_k<<<N_GRAPHS, 256>>>(sums, cnt, rw1, rb1, h1);
    readout2_k<<<N_GRAPHS, 128>>>(h1, rw2, rb2, rw3, rb3, out);
}

// round 10
// speedup vs baseline: 6.1632x; 1.3243x over previous
#include <cuda_runtime.h>
#include <cuda_fp16.h>
#include <cstdint>

#define DINL __device__ __forceinline__
#define N_NODES 25000
#define N_EDGES 300000
#define N_GRAPHS 256

// ---------------- helpers ----------------

DINL uint32_t smem_u32(const void* p) {
    uint32_t a;
    asm("{ .reg .u64 t; cvta.to.shared.u64 t, %1; cvt.u32.u64 %0, t; }" : "=r"(a) : "l"(p));
    return a;
}
DINL float sp(float x) {
    return fmaxf(x, 0.f) + __logf(1.f + __expf(-fabsf(x)));
}
DINL void red4(float* a, float x, float y, float z, float w) {
    asm volatile("red.global.add.v4.f32 [%0], {%1, %2, %3, %4};"
                 :: "l"(a), "f"(x), "f"(y), "f"(z), "f"(w) : "memory");
}
DINL uint32_t pkhf(float lo, float hi) {
    uint32_t u;
    asm("cvt.rn.f16x2.f32 %0, %1, %2;" : "=r"(u) : "f"(hi), "f"(lo));
    return u;
}
DINL void ldsm4(uint32_t& r0, uint32_t& r1, uint32_t& r2, uint32_t& r3, uint32_t a) {
    asm volatile("ldmatrix.sync.aligned.m8n8.x4.shared.b16 {%0,%1,%2,%3}, [%4];"
                 : "=r"(r0), "=r"(r1), "=r"(r2), "=r"(r3) : "r"(a));
}
DINL void mma_f16(float* d, const uint32_t* a, const uint32_t* b) {
    asm volatile("mma.sync.aligned.m16n8k16.row.col.f32.f16.f16.f32 "
                 "{%0,%1,%2,%3}, {%4,%5,%6,%7}, {%8,%9}, {%0,%1,%2,%3};"
                 : "+f"(d[0]), "+f"(d[1]), "+f"(d[2]), "+f"(d[3])
                 : "r"(a[0]), "r"(a[1]), "r"(a[2]), "r"(a[3]), "r"(b[0]), "r"(b[1]));
}
// K-major SW128 blocked-atom byte offset (swizzle affects only k-byte bits 4..6)
DINL int imgoff(int r, int k, int nra) {
    int base = ((r >> 3) + (k >> 6) * nra) * 1024 + (r & 7) * 128;
    int kb = ((k & 63) << 1) ^ ((r & 7) << 4);
    return base + kb;
}
// fragment-column -> actual-channel permutation (so each thread covers 4 contiguous chans)
DINL int chan(int p) {
    int q = p & 15;
    int cl = (q < 8) ? (((q >> 1) << 2) | (q & 1))
                     : ((((q - 8) >> 1) << 2) | 2 | (q & 1));
    return (p & ~15) | cl;
}

// ---------------- scratch ----------------

__device__ float g_x0[N_NODES * 128];
__device__ float g_xa[N_NODES * 256];
__device__ float g_xb[N_NODES * 256];
__device__ float g_agg[N_NODES * 256];
__device__ float g_sums[N_GRAPHS * 256];
__device__ float g_cnt[N_GRAPHS];
__device__ float g_h1[N_GRAPHS * 256];
__device__ __half g_imgE0[128 * 128];
__device__ __half g_imgE[3 * 256 * 256];
__device__ __half g_imgN0[256 * 128];
__device__ __half g_imgN[3 * 256 * 256];

// ---------------- small kernels ----------------

__global__ void zero_k(float* __restrict__ p, int n) {
    for (int i = blockIdx.x * blockDim.x + threadIdx.x; i < n; i += gridDim.x * blockDim.x)
        p[i] = 0.f;
}

__global__ void embed_k(const int* __restrict__ xa, const float* __restrict__ emb,
                        float* __restrict__ x0) {
    int i = blockIdx.x * blockDim.x + threadIdx.x;
    if (i < N_NODES * 128) {
        int v = i >> 7, c = i & 127;
        x0[i] = (c < 92) ? emb[xa[v] * 92 + c] : 0.f;
    }
}

// Weight image: img[p][k] = W[k][chan(p)] (transposed + col-permuted + swizzled fp16)
__global__ void prep_img_k(const float* __restrict__ w, __half* __restrict__ img,
                           int K, int N, int CRk, int CRn) {
    int i = blockIdx.x * blockDim.x + threadIdx.x;
    if (i >= N * K) return;
    int p = i / K, k = i - p * K;
    int c = chan(p);
    float v = (k < CRk && c < CRn) ? w[k * CRn + c] : 0.f;
    *(__half*)((char*)img + imgoff(p, k, N >> 3)) = __float2half(v);
}

// ---------------- fused HMMA tile kernel (512 threads, persistent) ----------------
// EDGE: A = f16(softplus(ea@W1+b1)) [128,K]; D = A@Bimg^T [128,N];
//       red agg[dst] += (D + b2) * x[src]
// NODE: A = f16(rows of a); D = A@Bimg^T; y = softplus(D + b)  (out width 256)
template <int K, int N, bool EDGE>
__global__ __launch_bounds__(512, 1)
void gemm_tile_k(const float* __restrict__ xs, const float* __restrict__ ea,
                 const int* __restrict__ src, const int* __restrict__ dst,
                 const float* __restrict__ w1, const float* __restrict__ b1,
                 const __half* __restrict__ bimg,
                 const float* __restrict__ bias, int CRb,
                 float* __restrict__ outp, int count, int ntiles) {
    constexpr int A_BYTES = 128 * K * 2;
    constexpr int B_BYTES = N * K * 2;
    constexpr int ASTR = 16 * 1024;        // A stride per 64-k block (128 rows)
    constexpr int BSTR = (N / 8) * 1024;   // B stride per 64-k block
    constexpr int NW = N / 4;              // cols per warp
    constexpr int NLD = NW / 16;           // B ldsm4s per k-step
    constexpr int NT8 = NW / 8;            // n8 tiles per warp

    extern __shared__ char smem[];
    char* As = smem;
    char* Bs = smem + A_BYTES;
    float* ws1 = (float*)(Bs + B_BYTES);   // [5][K]
    float* biass = ws1 + 5 * K;            // [N]
    float* eas = biass + N;                // [128][5]
    int* ss = (int*)(eas + 128 * 5);
    int* ds = ss + 128;

    const int tid = threadIdx.x;
    const int lane = tid & 31;
    const int warp = tid >> 5;
    const int wm = warp & 3, wn = warp >> 2;
    const int lr = lane & 7, lg = lane >> 3;
    const int tq = lane >> 2, tr = lane & 3;

    // ---- one-time staging: W1/b1, bias, B image ----
    if (EDGE) {
        for (int i = tid; i < 5 * K; i += 512) {
            int m = i / K, k = i - m * K;
            ws1[i] = (k < CRb) ? ((m < 4) ? w1[m * CRb + k] : b1[k]) : 0.f;
        }
    }
    for (int i = tid; i < N; i += 512) biass[i] = (i < CRb) ? bias[i] : 0.f;
    {
        const float4* g = (const float4*)bimg;
        float4* s = (float4*)Bs;
        for (int i = tid; i < B_BYTES / 16; i += 512) s[i] = g[i];
    }

    // lane-invariant MMA addressing
    const uint32_t smbA = smem_u32(As);
    const uint32_t smbB = smem_u32(Bs);
    const uint32_t sw = (uint32_t)(lr << 4);
    const int kofA = (lg >> 1) * 8;
    const int kofB = (lg & 1) * 8;
    uint32_t abase[2];
#pragma unroll
    for (int mi = 0; mi < 2; mi++)
        abase[mi] = smbA + (uint32_t)((wm * 4 + mi * 2 + (lg & 1)) * 1024 + lr * 128);
    uint32_t bb[NLD];
#pragma unroll
    for (int j = 0; j < NLD; j++)
        bb[j] = smbB + (uint32_t)((wn * (N / 32) + j * 2 + (lg >> 1)) * 1024 + lr * 128);

    for (int t = blockIdx.x; t < ntiles; t += gridDim.x) {
        __syncthreads();  // prior iteration fully done with smem

        // ---- per-tile staging ----
        if (EDGE) {
            for (int i = tid; i < 128; i += 512) {
                int eg = t * 128 + i;
                if (eg < count) {
                    ss[i] = src[eg];
                    ds[i] = dst[eg];
                    float4 v = reinterpret_cast<const float4*>(ea)[eg];
                    eas[i * 5 + 0] = v.x; eas[i * 5 + 1] = v.y;
                    eas[i * 5 + 2] = v.z; eas[i * 5 + 3] = v.w;
                } else {
                    ss[i] = -1; ds[i] = 0;
                    eas[i * 5 + 0] = 0.f; eas[i * 5 + 1] = 0.f;
                    eas[i * 5 + 2] = 0.f; eas[i * 5 + 3] = 0.f;
                }
            }
            __syncthreads();
        }

        // ---- build f16 A tile (swizzled) ----
        if (EDGE) {
            constexpr int PAIRS = K / 2;
            constexpr int EG = 512 / PAIRS;
            const int k = (tid & (PAIRS - 1)) * 2;
            const int grp = tid / PAIRS;
            float wa0 = ws1[k],         wa1 = ws1[k + 1];
            float wb0 = ws1[K + k],     wb1 = ws1[K + k + 1];
            float wc0 = ws1[2 * K + k], wc1 = ws1[2 * K + k + 1];
            float wd0 = ws1[3 * K + k], wd1 = ws1[3 * K + k + 1];
            float bb0 = ws1[4 * K + k], bb1 = ws1[4 * K + k + 1];
#pragma unroll 4
            for (int e = grp; e < 128; e += EG) {
                float a0 = eas[e * 5 + 0], a1 = eas[e * 5 + 1];
                float a2 = eas[e * 5 + 2], a3 = eas[e * 5 + 3];
                float z0 = fmaf(a0, wa0, fmaf(a1, wb0, fmaf(a2, wc0, fmaf(a3, wd0, bb0))));
                float z1 = fmaf(a0, wa1, fmaf(a1, wb1, fmaf(a2, wc1, fmaf(a3, wd1, bb1))));
                *(uint32_t*)(As + imgoff(e, k, 16)) = pkhf(sp(z0), sp(z1));
            }
        } else {
            constexpr int KT = K / 4;
            constexpr int VG = 512 / KT;
            const int k4 = (tid % KT) * 4;
            const int vg = tid / KT;
            const int v0 = t * 128;
#pragma unroll 4
            for (int v = vg; v < 128; v += VG) {
                int gv = v0 + v;
                float4 av = (gv < count)
                    ? __ldg((const float4*)(xs + (size_t)gv * K + k4))
                    : make_float4(0.f, 0.f, 0.f, 0.f);
                int off = imgoff(v, k4, 16);
                *(uint32_t*)(As + off) = pkhf(av.x, av.y);
                *(uint32_t*)(As + off + 4) = pkhf(av.z, av.w);
            }
        }
        __syncthreads();

        // ---- HMMA ----
        float acc[2][NT8][4];
#pragma unroll
        for (int mi = 0; mi < 2; mi++)
#pragma unroll
            for (int ni = 0; ni < NT8; ni++)
#pragma unroll
                for (int q = 0; q < 4; q++) acc[mi][ni][q] = 0.f;

#pragma unroll 2
        for (int k0 = 0; k0 < K; k0 += 16) {
            uint32_t blk = (uint32_t)(k0 >> 6);
            uint32_t akadd = blk * ASTR + ((uint32_t)(((k0 & 63) + kofA) << 1) ^ sw);
            uint32_t bkadd = blk * BSTR + ((uint32_t)(((k0 & 63) + kofB) << 1) ^ sw);

            uint32_t af[2][4];
#pragma unroll
            for (int mi = 0; mi < 2; mi++)
                ldsm4(af[mi][0], af[mi][1], af[mi][2], af[mi][3], abase[mi] + akadd);
            uint32_t bf[NLD][4];
#pragma unroll
            for (int j = 0; j < NLD; j++)
                ldsm4(bf[j][0], bf[j][1], bf[j][2], bf[j][3], bb[j] + bkadd);

#pragma unroll
            for (int mi = 0; mi < 2; mi++)
#pragma unroll
                for (int j = 0; j < NLD; j++) {
                    mma_f16(acc[mi][2 * j], af[mi], bf[j] + 0);
                    mma_f16(acc[mi][2 * j + 1], af[mi], bf[j] + 2);
                }
        }

        // ---- epilogue straight from fragments ----
        const int nb = wn * NW;
        if (EDGE) {
#pragma unroll
            for (int mi = 0; mi < 2; mi++) {
#pragma unroll
                for (int hf = 0; hf < 2; hf++) {
                    int row = wm * 32 + mi * 16 + tq + hf * 8;
                    int s = ss[row];
                    if (s < 0) continue;
                    const float* xrow = xs + (size_t)s * N;
                    float* arow = outp + (size_t)ds[row] * N;
#pragma unroll
                    for (int p = 0; p < NW / 16; p++) {
                        int c0 = nb + p * 16 + tr * 4;
                        float4 bv = *(const float4*)(biass + c0);
                        float4 xv = __ldg((const float4*)(xrow + c0));
                        float v0 = acc[mi][2 * p][2 * hf],     v1 = acc[mi][2 * p][2 * hf + 1];
                        float v2 = acc[mi][2 * p + 1][2 * hf], v3 = acc[mi][2 * p + 1][2 * hf + 1];
                        red4(arow + c0, (v0 + bv.x) * xv.x, (v1 + bv.y) * xv.y,
                             (v2 + bv.z) * xv.z, (v3 + bv.w) * xv.w);
                    }
                }
            }
        } else {
            const int v0b = t * 128;
#pragma unroll
            for (int mi = 0; mi < 2; mi++) {
#pragma unroll
                for (int hf = 0; hf < 2; hf++) {
                    int row = wm * 32 + mi * 16 + tq + hf * 8;
                    int gv = v0b + row;
                    if (gv >= count) continue;
                    float* yrow = outp + (size_t)gv * 256;
#pragma unroll
                    for (int p = 0; p < NW / 16; p++) {
                        int c0 = nb + p * 16 + tr * 4;
                        float4 bv = *(const float4*)(biass + c0);
                        float v0 = acc[mi][2 * p][2 * hf],     v1 = acc[mi][2 * p][2 * hf + 1];
                        float v2 = acc[mi][2 * p + 1][2 * hf], v3 = acc[mi][2 * p + 1][2 * hf + 1];
                        *(float4*)(yrow + c0) = make_float4(
                            sp(v0 + bv.x), sp(v1 + bv.y), sp(v2 + bv.z), sp(v3 + bv.w));
                    }
                }
            }
        }
    }
}

// ---------------- pooling / readout ----------------

__global__ void count_k(const int* __restrict__ batch, float* __restrict__ cnt, int N) {
    int i = blockIdx.x * blockDim.x + threadIdx.x;
    if (i < N) atomicAdd(&cnt[batch[i]], 1.f);
}

__global__ void pool_k(const float* __restrict__ x, const int* __restrict__ batch,
                       float* __restrict__ sums, int N) {
    __shared__ int bs[32];
    int t = threadIdx.x;
    int v0 = blockIdx.x * 32;
    if (t < 32) bs[t] = (v0 + t < N) ? batch[v0 + t] : -1;
    __syncthreads();
    int cur = bs[0];
    if (cur < 0) return;
    float run = 0.f;
    for (int v = 0; v < 32; v++) {
        int bg = bs[v];
        if (bg < 0) break;
        if (bg != cur) {
            atomicAdd(&sums[cur * 256 + t], run);
            run = 0.f;
            cur = bg;
        }
        run += x[(size_t)(v0 + v) * 256 + t];
    }
    atomicAdd(&sums[cur * 256 + t], run);
}

__global__ void readout1_k(const float* __restrict__ sums, const float* __restrict__ cnt,
                           const float* __restrict__ rw1, const float* __restrict__ rb1,
                           float* __restrict__ h1) {
    __shared__ float gv[256];
    int g = blockIdx.x, t = threadIdx.x;
    float cn = fmaxf(cnt[g], 1.f);
    gv[t] = sums[g * 256 + t] / cn;
    __syncthreads();
    float acc = rb1[t];
#pragma unroll 8
    for (int k = 0; k < 256; k++) acc = fmaf(gv[k], rw1[k * 256 + t], acc);
    h1[g * 256 + t] = sp(acc);
}

__global__ void readout2_k(const float* __restrict__ h1, const float* __restrict__ rw2,
                           const float* __restrict__ rb2, const float* __restrict__ rw3,
                           const float* __restrict__ rb3, float* __restrict__ out) {
    __shared__ float hv[256];
    __shared__ float part[4];
    int g = blockIdx.x, t = threadIdx.x;  // 128 threads
    hv[t] = h1[g * 256 + t];
    hv[t + 128] = h1[g * 256 + 128 + t];
    __syncthreads();
    float acc = rb2[t];
#pragma unroll 8
    for (int k = 0; k < 256; k++) acc = fmaf(hv[k], rw2[k * 128 + t], acc);
    float p = sp(acc) * rw3[t];
#pragma unroll
    for (int o = 16; o; o >>= 1) p += __shfl_down_sync(0xFFFFFFFFu, p, o);
    if ((t & 31) == 0) part[t >> 5] = p;
    __syncthreads();
    if (t == 0) out[g] = part[0] + part[1] + part[2] + part[3] + rb3[0];
}

// ---------------- launch ----------------

static constexpr int smem_sz(int K, int N) {
    return 128 * K * 2 + N * K * 2 + (5 * K + N + 128 * 5 + 256) * 4 + 64;
}

extern "C" void kernel_launch(void* const* d_in, const int* in_sizes, int n_in,
                              void* d_out, int out_size) {
    const int* x_atoms = (const int*)d_in[0];
    const int* eidx    = (const int*)d_in[1];
    const float* eattr = (const float*)d_in[2];
    const int* batch   = (const int*)d_in[3];
    const float* emb   = (const float*)d_in[4];
    const float* ew1_0 = (const float*)d_in[5];
    const float* eb1_0 = (const float*)d_in[6];
    const float* ew2_0 = (const float*)d_in[7];
    const float* eb2_0 = (const float*)d_in[8];
    const float* nw_0  = (const float*)d_in[9];
    const float* nb_0  = (const float*)d_in[10];
    const float* ew1   = (const float*)d_in[11];
    const float* eb1   = (const float*)d_in[12];
    const float* ew2   = (const float*)d_in[13];
    const float* eb2   = (const float*)d_in[14];
    const float* nw    = (const float*)d_in[15];
    const float* nb    = (const float*)d_in[16];
    const float* rw1   = (const float*)d_in[17];
    const float* rb1   = (const float*)d_in[18];
    const float* rw2   = (const float*)d_in[19];
    const float* rb2   = (const float*)d_in[20];
    const float* rw3   = (const float*)d_in[21];
    const float* rb3   = (const float*)d_in[22];
    float* out = (float*)d_out;

    const int* src = eidx;
    const int* dst = eidx + N_EDGES;

    float *x0, *xa, *xb, *agg, *sums, *cnt, *h1;
    __half *imgE0, *imgE, *imgN0, *imgN;
    cudaGetSymbolAddress((void**)&x0, g_x0);
    cudaGetSymbolAddress((void**)&xa, g_xa);
    cudaGetSymbolAddress((void**)&xb, g_xb);
    cudaGetSymbolAddress((void**)&agg, g_agg);
    cudaGetSymbolAddress((void**)&sums, g_sums);
    cudaGetSymbolAddress((void**)&cnt, g_cnt);
    cudaGetSymbolAddress((void**)&h1, g_h1);
    cudaGetSymbolAddress((void**)&imgE0, g_imgE0);
    cudaGetSymbolAddress((void**)&imgE, g_imgE);
    cudaGetSymbolAddress((void**)&imgN0, g_imgN0);
    cudaGetSymbolAddress((void**)&imgN, g_imgN);

    cudaFuncSetAttribute(gemm_tile_k<256, 256, true>,
                         cudaFuncAttributeMaxDynamicSharedMemorySize, smem_sz(256, 256));
    cudaFuncSetAttribute(gemm_tile_k<128, 128, true>,
                         cudaFuncAttributeMaxDynamicSharedMemorySize, smem_sz(128, 128));
    cudaFuncSetAttribute(gemm_tile_k<256, 256, false>,
                         cudaFuncAttributeMaxDynamicSharedMemorySize, smem_sz(256, 256));
    cudaFuncSetAttribute(gemm_tile_k<128, 256, false>,
                         cudaFuncAttributeMaxDynamicSharedMemorySize, smem_sz(128, 256));

    // weight images (transposed + col-permuted + swizzled fp16)
    prep_img_k<<<(128 * 128 + 255) / 256, 256>>>(ew2_0, imgE0, 128, 128, 92, 92);
    prep_img_k<<<(256 * 128 + 255) / 256, 256>>>(nw_0, imgN0, 128, 256, 92, 256);
    for (int i = 0; i < 3; i++) {
        prep_img_k<<<(256 * 256 + 255) / 256, 256>>>(ew2 + i * 65536, imgE + i * 65536,
                                                     256, 256, 256, 256);
        prep_img_k<<<(256 * 256 + 255) / 256, 256>>>(nw + i * 65536, imgN + i * 65536,
                                                     256, 256, 256, 256);
    }

    embed_k<<<(N_NODES * 128 + 255) / 256, 256>>>(x_atoms, emb, x0);

    const int EB = (N_EDGES + 127) / 128;   // 2344
    const int NB = (N_NODES + 127) / 128;   // 196
    const int GRID = 148;

    // layer 0 (92 padded to 128)
    zero_k<<<4096, 256>>>(agg, N_NODES * 128);
    gemm_tile_k<128, 128, true><<<GRID, 512, smem_sz(128, 128)>>>(
        x0, eattr, src, dst, ew1_0, eb1_0, imgE0, eb2_0, 92, agg, N_EDGES, EB);
    gemm_tile_k<128, 256, false><<<GRID, 512, smem_sz(128, 256)>>>(
        agg, nullptr, nullptr, nullptr, nullptr, nullptr, imgN0, nb_0, 256, xa,
        N_NODES, NB);

    // layers 1..3
    const float* xin = xa;
    float* xout = xb;
    for (int i = 0; i < 3; i++) {
        zero_k<<<8192, 256>>>(agg, N_NODES * 256);
        gemm_tile_k<256, 256, true><<<GRID, 512, smem_sz(256, 256)>>>(
            xin, eattr, src, dst, ew1 + i * 4 * 256, eb1 + i * 256,
            imgE + i * 65536, eb2 + i * 256, 256, agg, N_EDGES, EB);
        gemm_tile_k<256, 256, false><<<GRID, 512, smem_sz(256, 256)>>>(
            agg, nullptr, nullptr, nullptr, nullptr, nullptr,
            imgN + i * 65536, nb + i * 256, 256, xout, N_NODES, NB);
        const float* t = xin;
        xin = xout;
        xout = (float*)t;
    }

    // pooling + readout
    zero_k<<<64, 256>>>(sums, N_GRAPHS * 256);
    zero_k<<<1, 256>>>(cnt, N_GRAPHS);
    count_k<<<(N_NODES + 255) / 256, 256>>>(batch, cnt, N_NODES);
    pool_k<<<(N_NODES + 31) / 32, 256>>>(xin, batch, sums, N_NODES);
    readout1_k<<<N_GRAPHS, 256>>>(sums, cnt, rw1, rb1, h1);
    readout2_k<<<N_GRAPHS, 128>>>(h1, rw2, rb2, rw3, rb3, out);
}

// round 11
// speedup vs baseline: 6.1928x; 1.0048x over previous
#include <cuda_runtime.h>
#include <cuda_fp16.h>
#include <cstdint>

#define DINL __device__ __forceinline__
#define N_NODES 25000
#define N_EDGES 300000
#define N_GRAPHS 256

// ---------------- helpers ----------------

DINL uint32_t smem_u32(const void* p) {
    uint32_t a;
    asm("{ .reg .u64 t; cvta.to.shared.u64 t, %1; cvt.u32.u64 %0, t; }" : "=r"(a) : "l"(p));
    return a;
}
DINL float sp(float x) {
    return fmaxf(x, 0.f) + __logf(1.f + __expf(-fabsf(x)));
}
DINL void red4(float* a, float x, float y, float z, float w) {
    asm volatile("red.global.add.v4.f32 [%0], {%1, %2, %3, %4};"
                 :: "l"(a), "f"(x), "f"(y), "f"(z), "f"(w) : "memory");
}
DINL uint32_t pkhf(float lo, float hi) {
    uint32_t u;
    asm("cvt.rn.f16x2.f32 %0, %1, %2;" : "=r"(u) : "f"(hi), "f"(lo));
    return u;
}
DINL void ldsm4(uint32_t& r0, uint32_t& r1, uint32_t& r2, uint32_t& r3, uint32_t a) {
    asm volatile("ldmatrix.sync.aligned.m8n8.x4.shared.b16 {%0,%1,%2,%3}, [%4];"
                 : "=r"(r0), "=r"(r1), "=r"(r2), "=r"(r3) : "r"(a));
}
DINL void mma_f16(float* d, const uint32_t* a, const uint32_t* b) {
    asm volatile("mma.sync.aligned.m16n8k16.row.col.f32.f16.f16.f32 "
                 "{%0,%1,%2,%3}, {%4,%5,%6,%7}, {%8,%9}, {%0,%1,%2,%3};"
                 : "+f"(d[0]), "+f"(d[1]), "+f"(d[2]), "+f"(d[3])
                 : "r"(a[0]), "r"(a[1]), "r"(a[2]), "r"(a[3]), "r"(b[0]), "r"(b[1]));
}
// K-major SW128 blocked-atom byte offset (swizzle affects only k-byte bits 4..6)
DINL int imgoff(int r, int k, int nra) {
    int base = ((r >> 3) + (k >> 6) * nra) * 1024 + (r & 7) * 128;
    int kb = ((k & 63) << 1) ^ ((r & 7) << 4);
    return base + kb;
}
// fragment-column -> actual-channel permutation
DINL int chan(int p) {
    int q = p & 15;
    int cl = (q < 8) ? (((q >> 1) << 2) | (q & 1))
                     : ((((q - 8) >> 1) << 2) | 2 | (q & 1));
    return (p & ~15) | cl;
}

// build one edge's A entries at k-pair (k, k+1)
template <int K>
DINL void build_edge(char* As, const float* ws1, const float* eas, int e, int k) {
    float a0 = eas[e * 5 + 0], a1 = eas[e * 5 + 1];
    float a2 = eas[e * 5 + 2], a3 = eas[e * 5 + 3];
    float z0 = fmaf(a0, ws1[k],
               fmaf(a1, ws1[K + k],
               fmaf(a2, ws1[2 * K + k],
               fmaf(a3, ws1[3 * K + k], ws1[4 * K + k]))));
    float z1 = fmaf(a0, ws1[k + 1],
               fmaf(a1, ws1[K + k + 1],
               fmaf(a2, ws1[2 * K + k + 1],
               fmaf(a3, ws1[3 * K + k + 1], ws1[4 * K + k + 1]))));
    *(uint32_t*)(As + imgoff(e, k, 16)) = pkhf(sp(z0), sp(z1));
}

template <int NLD, int NT8>
DINL void mma_step(uint32_t ab0, uint32_t ab1, const uint32_t* bb,
                   uint32_t akadd, uint32_t bkadd, float (*acc)[NT8][4]) {
    uint32_t af0[4], af1[4];
    ldsm4(af0[0], af0[1], af0[2], af0[3], ab0 + akadd);
    ldsm4(af1[0], af1[1], af1[2], af1[3], ab1 + akadd);
    uint32_t bf[NLD][4];
#pragma unroll
    for (int j = 0; j < NLD; j++)
        ldsm4(bf[j][0], bf[j][1], bf[j][2], bf[j][3], bb[j] + bkadd);
#pragma unroll
    for (int j = 0; j < NLD; j++) {
        mma_f16(acc[0][2 * j], af0, bf[j]);
        mma_f16(acc[0][2 * j + 1], af0, bf[j] + 2);
        mma_f16(acc[1][2 * j], af1, bf[j]);
        mma_f16(acc[1][2 * j + 1], af1, bf[j] + 2);
    }
}

// ---------------- scratch ----------------

__device__ float g_x0[N_NODES * 128];
__device__ float g_xa[N_NODES * 256];
__device__ float g_xb[N_NODES * 256];
__device__ float g_agg[N_NODES * 256];   // invariant: all-zero between runs
__device__ float g_sums[N_GRAPHS * 256];
__device__ float g_cnt[N_GRAPHS];
__device__ __half g_imgE0[128 * 128];
__device__ __half g_imgE[3 * 256 * 256];
__device__ __half g_imgN0[256 * 128];
__device__ __half g_imgN[3 * 256 * 256];

// ---------------- small kernels ----------------

__global__ void zero2_k(float* __restrict__ a, int na, float* __restrict__ b, int nb) {
    int i = blockIdx.x * blockDim.x + threadIdx.x;
    if (i < na) a[i] = 0.f;
    if (i < nb) b[i] = 0.f;
}

__global__ void embed_k(const int* __restrict__ xa, const float* __restrict__ emb,
                        float* __restrict__ x0) {
    int i = blockIdx.x * blockDim.x + threadIdx.x;
    if (i < N_NODES * 128) {
        int v = i >> 7, c = i & 127;
        x0[i] = (c < 92) ? emb[xa[v] * 92 + c] : 0.f;
    }
}

DINL void prep_one(const float* w, __half* img, int K, int N, int CRk, int CRn, int i) {
    int p = i / K, k = i - p * K;
    int c = chan(p);
    float v = (k < CRk && c < CRn) ? w[k * CRn + c] : 0.f;
    *(__half*)((char*)img + imgoff(p, k, N >> 3)) = __float2half(v);
}

// all 8 weight images in one launch
__global__ void prep_all_k(const float* __restrict__ ew2_0, const float* __restrict__ nw_0,
                           const float* __restrict__ ew2, const float* __restrict__ nw,
                           __half* __restrict__ imgE0, __half* __restrict__ imgN0,
                           __half* __restrict__ imgE, __half* __restrict__ imgN) {
    int i = blockIdx.x * blockDim.x + threadIdx.x;
    if (i < 16384) {
        prep_one(ew2_0, imgE0, 128, 128, 92, 92, i);
    } else if (i < 16384 + 32768) {
        prep_one(nw_0, imgN0, 128, 256, 92, 256, i - 16384);
    } else if (i < 16384 + 32768 + 3 * 65536) {
        int j = i - 16384 - 32768;
        int l = j >> 16;
        prep_one(ew2 + l * 65536, imgE + l * 65536, 256, 256, 256, 256, j & 65535);
    } else if (i < 16384 + 32768 + 6 * 65536) {
        int j = i - 16384 - 32768 - 3 * 65536;
        int l = j >> 16;
        prep_one(nw + l * 65536, imgN + l * 65536, 256, 256, 256, 256, j & 65535);
    }
}

// ---------------- fused HMMA tile kernel (512 threads, persistent, pipelined) ----------------
template <int K, int N, bool EDGE>
__global__ __launch_bounds__(512, 1)
void gemm_tile_k(const float* __restrict__ xs, const float* __restrict__ ea,
                 const int* __restrict__ src, const int* __restrict__ dst,
                 const float* __restrict__ w1, const float* __restrict__ b1,
                 const __half* __restrict__ bimg, const float* __restrict__ bias,
                 int CRb, float* __restrict__ outp, float* __restrict__ zbuf,
                 int count, int ntiles) {
    constexpr int A_BYTES = 128 * K * 2;
    constexpr int B_BYTES = N * K * 2;
    constexpr int ASTR = 16 * 1024;
    constexpr int BSTR = (N / 8) * 1024;
    constexpr int KH = K / 2;
    constexpr int STEPS = KH / 16;        // mma steps per k-half
    constexpr int NWP = N / 8;            // cols per warp per pass
    constexpr int NLD = NWP / 16;
    constexpr int NT8 = NWP / 8;
    constexpr int PEP = NWP / 16;
    // edge build geometry (per half)
    constexpr int PAIRS_H = K / 4;
    constexpr int EG_H = 512 / PAIRS_H;
    constexpr int EPT_H = 128 / EG_H;
    constexpr int EPS = EPT_H / STEPS;    // edges built per interleave step
    // node build geometry (per half)
    constexpr int KTH = K / 8;
    constexpr int VG_H = 512 / KTH;       // rows-per-thread = STEPS

    extern __shared__ char smem[];
    char* As = smem;
    char* Bs = smem + A_BYTES;
    float* ws1 = (float*)(Bs + B_BYTES);   // [5][K]
    float* biass = ws1 + 5 * K;            // [N]
    float* eas = biass + N;                // [128][5]
    int* ss = (int*)(eas + 128 * 5);
    int* ds = ss + 128;

    const int tid = threadIdx.x;
    const int lane = tid & 31;
    const int warp = tid >> 5;
    const int wm = warp & 3, wn = warp >> 2;
    const int lr = lane & 7, lg = lane >> 3;
    const int tq = lane >> 2, tr = lane & 3;

    // one-time staging
    if (EDGE) {
        for (int i = tid; i < 5 * K; i += 512) {
            int m = i / K, k = i - m * K;
            ws1[i] = (k < CRb) ? ((m < 4) ? w1[m * CRb + k] : b1[k]) : 0.f;
        }
    }
    for (int i = tid; i < N; i += 512) biass[i] = (i < CRb) ? bias[i] : 0.f;
    {
        const float4* g = (const float4*)bimg;
        float4* s = (float4*)Bs;
        for (int i = tid; i < B_BYTES / 16; i += 512) s[i] = g[i];
    }

    const uint32_t smbA = smem_u32(As);
    const uint32_t smbB = smem_u32(Bs);
    const uint32_t sw = (uint32_t)(lr << 4);
    const int kofA = (lg >> 1) * 8;
    const int kofB = (lg & 1) * 8;
    const uint32_t ab0 = smbA + (uint32_t)((wm * 4 + (lg & 1)) * 1024 + lr * 128);
    const uint32_t ab1 = ab0 + 2 * 1024;

    // build-thread mappings (computed unconditionally; cheap)
    const int kp = (tid & (PAIRS_H - 1)) * 2;   // edge: k-pair within half
    const int grp = tid / PAIRS_H;              // edge: edge group
    const int kq = tid & (KTH - 1);             // node: float4 slot within half
    const int k4 = kq * 4;
    const int vg = tid / KTH;                   // node: row group

    for (int t = blockIdx.x; t < ntiles; t += gridDim.x) {
        __syncthreads();  // previous tile fully done with smem

        const int v0 = t * 128;

        if (EDGE) {
            for (int i = tid; i < 128; i += 512) {
                int eg = t * 128 + i;
                if (eg < count) {
                    ss[i] = src[eg];
                    ds[i] = dst[eg];
                    float4 v = reinterpret_cast<const float4*>(ea)[eg];
                    eas[i * 5 + 0] = v.x; eas[i * 5 + 1] = v.y;
                    eas[i * 5 + 2] = v.z; eas[i * 5 + 3] = v.w;
                } else {
                    ss[i] = -1; ds[i] = 0;
                    eas[i * 5 + 0] = 0.f; eas[i * 5 + 1] = 0.f;
                    eas[i * 5 + 2] = 0.f; eas[i * 5 + 3] = 0.f;
                }
            }
            __syncthreads();
        }

        // ---- build half1 (and prefetch half2 for NODE) ----
        float4 pre[STEPS];
        if (EDGE) {
#pragma unroll
            for (int i = 0; i < EPT_H; i++)
                build_edge<K>(As, ws1, eas, grp + i * EG_H, kp);
        } else {
#pragma unroll
            for (int i = 0; i < STEPS; i++) {
                int gv = v0 + vg + i * VG_H;
                pre[i] = (gv < count)
                    ? __ldg((const float4*)(xs + (size_t)gv * K + k4 + KH))
                    : make_float4(0.f, 0.f, 0.f, 0.f);
            }
#pragma unroll
            for (int i = 0; i < STEPS; i++) {
                int v = vg + i * VG_H;
                int gv = v0 + v;
                float4 av = (gv < count)
                    ? __ldg((const float4*)(xs + (size_t)gv * K + k4))
                    : make_float4(0.f, 0.f, 0.f, 0.f);
                int off = imgoff(v, k4, 16);
                *(uint32_t*)(As + off) = pkhf(av.x, av.y);
                *(uint32_t*)(As + off + 4) = pkhf(av.z, av.w);
            }
        }
        __syncthreads();

        float acc[2][NT8][4];
        uint32_t bb[NLD];

        // ================= pass np = 0 =================
#pragma unroll
        for (int mi = 0; mi < 2; mi++)
#pragma unroll
            for (int ni = 0; ni < NT8; ni++)
#pragma unroll
                for (int q = 0; q < 4; q++) acc[mi][ni][q] = 0.f;
        {
            int batom = (wn * (N / 4)) >> 3;
#pragma unroll
            for (int j = 0; j < NLD; j++)
                bb[j] = smbB + (uint32_t)((batom + j * 2 + (lg >> 1)) * 1024 + lr * 128);
        }
        // sweep k-half1, interleaved with building half2
#pragma unroll
        for (int s = 0; s < STEPS; s++) {
            int k0 = s * 16;
            uint32_t blk = (uint32_t)(k0 >> 6);
            uint32_t akadd = blk * ASTR + ((uint32_t)(((k0 & 63) + kofA) << 1) ^ sw);
            uint32_t bkadd = blk * BSTR + ((uint32_t)(((k0 & 63) + kofB) << 1) ^ sw);
            mma_step<NLD, NT8>(ab0, ab1, bb, akadd, bkadd, acc);
            if (EDGE) {
#pragma unroll
                for (int j = 0; j < EPS; j++)
                    build_edge<K>(As, ws1, eas, grp + (s * EPS + j) * EG_H, kp + KH);
            } else {
                int v = vg + s * VG_H;
                int off = imgoff(v, k4 + KH, 16);
                *(uint32_t*)(As + off) = pkhf(pre[s].x, pre[s].y);
                *(uint32_t*)(As + off + 4) = pkhf(pre[s].z, pre[s].w);
            }
        }
        __syncthreads();  // half2 built
        // sweep k-half2
#pragma unroll
        for (int s = 0; s < STEPS; s++) {
            int k0 = KH + s * 16;
            uint32_t blk = (uint32_t)(k0 >> 6);
            uint32_t akadd = blk * ASTR + ((uint32_t)(((k0 & 63) + kofA) << 1) ^ sw);
            uint32_t bkadd = blk * BSTR + ((uint32_t)(((k0 & 63) + kofB) << 1) ^ sw);
            mma_step<NLD, NT8>(ab0, ab1, bb, akadd, bkadd, acc);
        }
        // epilogue np = 0
#pragma unroll
        for (int np = 0; np < 1; np++) {}  // (structure kept flat below)
        {
            const int colb = wn * (N / 4);
            if (EDGE) {
#pragma unroll
                for (int mi = 0; mi < 2; mi++)
#pragma unroll
                    for (int hf = 0; hf < 2; hf++) {
                        int row = wm * 32 + mi * 16 + tq + hf * 8;
                        int s = ss[row];
                        if (s < 0) continue;
                        const float* xrow = xs + (size_t)s * N;
                        float* arow = outp + (size_t)ds[row] * N;
#pragma unroll
                        for (int p = 0; p < PEP; p++) {
                            int c0 = colb + p * 16 + tr * 4;
                            float4 bv = *(const float4*)(biass + c0);
                            float4 xv = __ldg((const float4*)(xrow + c0));
                            float a0 = acc[mi][2 * p][2 * hf], a1 = acc[mi][2 * p][2 * hf + 1];
                            float a2 = acc[mi][2 * p + 1][2 * hf], a3 = acc[mi][2 * p + 1][2 * hf + 1];
                            red4(arow + c0, (a0 + bv.x) * xv.x, (a1 + bv.y) * xv.y,
                                 (a2 + bv.z) * xv.z, (a3 + bv.w) * xv.w);
                        }
                    }
            } else {
#pragma unroll
                for (int mi = 0; mi < 2; mi++)
#pragma unroll
                    for (int hf = 0; hf < 2; hf++) {
                        int row = wm * 32 + mi * 16 + tq + hf * 8;
                        int gv = v0 + row;
                        if (gv >= count) continue;
                        float* yrow = outp + (size_t)gv * 256;
#pragma unroll
                        for (int p = 0; p < PEP; p++) {
                            int c0 = colb + p * 16 + tr * 4;
                            float4 bv = *(const float4*)(biass + c0);
                            float a0 = acc[mi][2 * p][2 * hf], a1 = acc[mi][2 * p][2 * hf + 1];
                            float a2 = acc[mi][2 * p + 1][2 * hf], a3 = acc[mi][2 * p + 1][2 * hf + 1];
                            *(float4*)(yrow + c0) = make_float4(
                                sp(a0 + bv.x), sp(a1 + bv.y), sp(a2 + bv.z), sp(a3 + bv.w));
                        }
                    }
            }
        }

        // ================= pass np = 1 =================
#pragma unroll
        for (int mi = 0; mi < 2; mi++)
#pragma unroll
            for (int ni = 0; ni < NT8; ni++)
#pragma unroll
                for (int q = 0; q < 4; q++) acc[mi][ni][q] = 0.f;
        {
            int batom = (wn * (N / 4) + NWP) >> 3;
#pragma unroll
            for (int j = 0; j < NLD; j++)
                bb[j] = smbB + (uint32_t)((batom + j * 2 + (lg >> 1)) * 1024 + lr * 128);
        }
#pragma unroll
        for (int s = 0; s < 2 * STEPS; s++) {
            int k0 = s * 16;
            uint32_t blk = (uint32_t)(k0 >> 6);
            uint32_t akadd = blk * ASTR + ((uint32_t)(((k0 & 63) + kofA) << 1) ^ sw);
            uint32_t bkadd = blk * BSTR + ((uint32_t)(((k0 & 63) + kofB) << 1) ^ sw);
            mma_step<NLD, NT8>(ab0, ab1, bb, akadd, bkadd, acc);
        }
        // epilogue np = 1
        {
            const int colb = wn * (N / 4) + NWP;
            if (EDGE) {
#pragma unroll
                for (int mi = 0; mi < 2; mi++)
#pragma unroll
                    for (int hf = 0; hf < 2; hf++) {
                        int row = wm * 32 + mi * 16 + tq + hf * 8;
                        int s = ss[row];
                        if (s < 0) continue;
                        const float* xrow = xs + (size_t)s * N;
                        float* arow = outp + (size_t)ds[row] * N;
#pragma unroll
                        for (int p = 0; p < PEP; p++) {
                            int c0 = colb + p * 16 + tr * 4;
                            float4 bv = *(const float4*)(biass + c0);
                            float4 xv = __ldg((const float4*)(xrow + c0));
                            float a0 = acc[mi][2 * p][2 * hf], a1 = acc[mi][2 * p][2 * hf + 1];
                            float a2 = acc[mi][2 * p + 1][2 * hf], a3 = acc[mi][2 * p + 1][2 * hf + 1];
                            red4(arow + c0, (a0 + bv.x) * xv.x, (a1 + bv.y) * xv.y,
                                 (a2 + bv.z) * xv.z, (a3 + bv.w) * xv.w);
                        }
                    }
            } else {
#pragma unroll
                for (int mi = 0; mi < 2; mi++)
#pragma unroll
                    for (int hf = 0; hf < 2; hf++) {
                        int row = wm * 32 + mi * 16 + tq + hf * 8;
                        int gv = v0 + row;
                        if (gv >= count) continue;
                        float* yrow = outp + (size_t)gv * 256;
#pragma unroll
                        for (int p = 0; p < PEP; p++) {
                            int c0 = colb + p * 16 + tr * 4;
                            float4 bv = *(const float4*)(biass + c0);
                            float a0 = acc[mi][2 * p][2 * hf], a1 = acc[mi][2 * p][2 * hf + 1];
                            float a2 = acc[mi][2 * p + 1][2 * hf], a3 = acc[mi][2 * p + 1][2 * hf + 1];
                            *(float4*)(yrow + c0) = make_float4(
                                sp(a0 + bv.x), sp(a1 + bv.y), sp(a2 + bv.z), sp(a3 + bv.w));
                        }
                    }
            }
        }

        // node: restore agg-is-zero invariant on everything this tile consumed
        if (!EDGE) {
            const float4 z4 = make_float4(0.f, 0.f, 0.f, 0.f);
#pragma unroll
            for (int i = 0; i < STEPS; i++) {
                int gv = v0 + vg + i * VG_H;
                if (gv < count) {
                    *(float4*)(zbuf + (size_t)gv * K + k4) = z4;
                    *(float4*)(zbuf + (size_t)gv * K + k4 + KH) = z4;
                }
            }
        }
    }
}

// ---------------- pooling / readout ----------------

__global__ void pool_k(const float* __restrict__ x, const int* __restrict__ batch,
                       float* __restrict__ sums, float* __restrict__ cnt, int N) {
    __shared__ int bs[32];
    int t = threadIdx.x;
    int v0 = blockIdx.x * 32;
    if (t < 32) bs[t] = (v0 + t < N) ? batch[v0 + t] : -1;
    __syncthreads();
    int cur = bs[0];
    if (cur < 0) return;
    float run = 0.f;
    int rl = 0;
    for (int v = 0; v < 32; v++) {
        int bg = bs[v];
        if (bg < 0) break;
        if (bg != cur) {
            atomicAdd(&sums[cur * 256 + t], run);
            if (t == 0) atomicAdd(&cnt[cur], (float)rl);
            run = 0.f; rl = 0; cur = bg;
        }
        run += x[(size_t)(v0 + v) * 256 + t];
        rl++;
    }
    atomicAdd(&sums[cur * 256 + t], run);
    if (t == 0) atomicAdd(&cnt[cur], (float)rl);
}

__global__ void readout_k(const float* __restrict__ sums, const float* __restrict__ cnt,
                          const float* __restrict__ rw1, const float* __restrict__ rb1,
                          const float* __restrict__ rw2, const float* __restrict__ rb2,
                          const float* __restrict__ rw3, const float* __restrict__ rb3,
                          float* __restrict__ out) {
    __shared__ float gv[256];
    __shared__ float hv[256];
    __shared__ float part[4];
    int g = blockIdx.x, t = threadIdx.x;  // 256 threads
    float cn = fmaxf(cnt[g], 1.f);
    gv[t] = sums[g * 256 + t] / cn;
    __syncthreads();
    float acc = rb1[t];
#pragma unroll 8
    for (int k = 0; k < 256; k++) acc = fmaf(gv[k], rw1[k * 256 + t], acc);
    hv[t] = sp(acc);
    __syncthreads();
    if (t < 128) {
        float a2 = rb2[t];
#pragma unroll 8
        for (int k = 0; k < 256; k++) a2 = fmaf(hv[k], rw2[k * 128 + t], a2);
        float p = sp(a2) * rw3[t];
#pragma unroll
        for (int o = 16; o; o >>= 1) p += __shfl_down_sync(0xFFFFFFFFu, p, o);
        if ((t & 31) == 0) part[t >> 5] = p;
    }
    __syncthreads();
    if (t == 0) out[g] = part[0] + part[1] + part[2] + part[3] + rb3[0];
}

// ---------------- launch ----------------

static constexpr int smem_sz(int K, int N) {
    return 128 * K * 2 + N * K * 2 + (5 * K + N + 128 * 5 + 256) * 4 + 64;
}

extern "C" void kernel_launch(void* const* d_in, const int* in_sizes, int n_in,
                              void* d_out, int out_size) {
    const int* x_atoms = (const int*)d_in[0];
    const int* eidx    = (const int*)d_in[1];
    const float* eattr = (const float*)d_in[2];
    const int* batch   = (const int*)d_in[3];
    const float* emb   = (const float*)d_in[4];
    const float* ew1_0 = (const float*)d_in[5];
    const float* eb1_0 = (const float*)d_in[6];
    const float* ew2_0 = (const float*)d_in[7];
    const float* eb2_0 = (const float*)d_in[8];
    const float* nw_0  = (const float*)d_in[9];
    const float* nb_0  = (const float*)d_in[10];
    const float* ew1   = (const float*)d_in[11];
    const float* eb1   = (const float*)d_in[12];
    const float* ew2   = (const float*)d_in[13];
    const float* eb2   = (const float*)d_in[14];
    const float* nw    = (const float*)d_in[15];
    const float* nb    = (const float*)d_in[16];
    const float* rw1   = (const float*)d_in[17];
    const float* rb1   = (const float*)d_in[18];
    const float* rw2   = (const float*)d_in[19];
    const float* rb2   = (const float*)d_in[20];
    const float* rw3   = (const float*)d_in[21];
    const float* rb3   = (const float*)d_in[22];
    float* out = (float*)d_out;

    const int* src = eidx;
    const int* dst = eidx + N_EDGES;

    float *x0, *xa, *xb, *agg, *sums, *cnt;
    __half *imgE0, *imgE, *imgN0, *imgN;
    cudaGetSymbolAddress((void**)&x0, g_x0);
    cudaGetSymbolAddress((void**)&xa, g_xa);
    cudaGetSymbolAddress((void**)&xb, g_xb);
    cudaGetSymbolAddress((void**)&agg, g_agg);
    cudaGetSymbolAddress((void**)&sums, g_sums);
    cudaGetSymbolAddress((void**)&cnt, g_cnt);
    cudaGetSymbolAddress((void**)&imgE0, g_imgE0);
    cudaGetSymbolAddress((void**)&imgE, g_imgE);
    cudaGetSymbolAddress((void**)&imgN0, g_imgN0);
    cudaGetSymbolAddress((void**)&imgN, g_imgN);

    cudaFuncSetAttribute(gemm_tile_k<256, 256, true>,
                         cudaFuncAttributeMaxDynamicSharedMemorySize, smem_sz(256, 256));
    cudaFuncSetAttribute(gemm_tile_k<128, 128, true>,
                         cudaFuncAttributeMaxDynamicSharedMemorySize, smem_sz(128, 128));
    cudaFuncSetAttribute(gemm_tile_k<256, 256, false>,
                         cudaFuncAttributeMaxDynamicSharedMemorySize, smem_sz(256, 256));
    cudaFuncSetAttribute(gemm_tile_k<128, 256, false>,
                         cudaFuncAttributeMaxDynamicSharedMemorySize, smem_sz(128, 256));

    // all weight images in one launch
    prep_all_k<<<(16384 + 32768 + 6 * 65536 + 255) / 256, 256>>>(
        ew2_0, nw_0, ew2, nw, imgE0, imgN0, imgE, imgN);

    embed_k<<<(N_NODES * 128 + 255) / 256, 256>>>(x_atoms, emb, x0);

    const int EB = (N_EDGES + 127) / 128;   // 2344
    const int NB = (N_NODES + 127) / 128;   // 196
    const int GRID = 148;

    // layer 0 (92 padded to 128); agg is all-zero by invariant
    gemm_tile_k<128, 128, true><<<GRID, 512, smem_sz(128, 128)>>>(
        x0, eattr, src, dst, ew1_0, eb1_0, imgE0, eb2_0, 92, agg, nullptr, N_EDGES, EB);
    gemm_tile_k<128, 256, false><<<GRID, 512, smem_sz(128, 256)>>>(
        agg, nullptr, nullptr, nullptr, nullptr, nullptr, imgN0, nb_0, 256, xa, agg,
        N_NODES, NB);

    // layers 1..3
    const float* xin = xa;
    float* xout = xb;
    for (int i = 0; i < 3; i++) {
        gemm_tile_k<256, 256, true><<<GRID, 512, smem_sz(256, 256)>>>(
            xin, eattr, src, dst, ew1 + i * 4 * 256, eb1 + i * 256,
            imgE + i * 65536, eb2 + i * 256, 256, agg, nullptr, N_EDGES, EB);
        gemm_tile_k<256, 256, false><<<GRID, 512, smem_sz(256, 256)>>>(
            agg, nullptr, nullptr, nullptr, nullptr, nullptr,
            imgN + i * 65536, nb + i * 256, 256, xout, agg, N_NODES, NB);
        const float* t = xin;
        xin = xout;
        xout = (float*)t;
    }

    // pooling + readout
    zero2_k<<<(N_GRAPHS * 256 + 255) / 256, 256>>>(sums, N_GRAPHS * 256, cnt, N_GRAPHS);
    pool_k<<<(N_NODES + 31) / 32, 256>>>(xin, batch, sums, cnt, N_NODES);
    readout_k<<<N_GRAPHS, 256>>>(sums, cnt, rw1, rb1, rw2, rb2, rw3, rb3, out);
}